// round 1
// baseline (speedup 1.0000x reference)
#include <cuda_runtime.h>
#include <math.h>

// Problem constants
#define BB   4
#define LL   2048
#define DIMC 1024
#define DFFC 4096
#define MROWS (BB*LL)        // 8192
#define NCHUNK 16
#define CHUNK  (LL/NCHUNK)   // 128
#define EPSLN 1e-5f

// Scratch (device globals: allocation-free rule)
__device__ float  g_h[(size_t)MROWS*DIMC];     // h1 then h2 (reused)
__device__ float  g_y1[(size_t)MROWS*DIMC];    // conv + x residual
__device__ float  g_act[(size_t)MROWS*DFFC];   // silu(h2@w1+b1)
__device__ float2 g_chunkS[BB*NCHUNK*DIMC];    // chunk partial end-states
__device__ float2 g_initS[BB*NCHUNK*DIMC];     // chunk initial states

// ---------------------------------------------------------------------------
// LayerNorm: one block per row, 256 threads x 4 floats
// ---------------------------------------------------------------------------
__global__ __launch_bounds__(256) void ln_kernel(
    const float* __restrict__ x, const float* __restrict__ g,
    const float* __restrict__ b, float* __restrict__ out)
{
    int row = blockIdx.x;
    size_t base = (size_t)row * DIMC;
    float4 v = ((const float4*)(x + base))[threadIdx.x];

    float s  = v.x + v.y + v.z + v.w;
    float sq = v.x*v.x + v.y*v.y + v.z*v.z + v.w*v.w;
    #pragma unroll
    for (int o = 16; o > 0; o >>= 1) {
        s  += __shfl_xor_sync(0xffffffffu, s,  o);
        sq += __shfl_xor_sync(0xffffffffu, sq, o);
    }
    __shared__ float ss[8], ssq[8];
    int w = threadIdx.x >> 5, lane = threadIdx.x & 31;
    if (lane == 0) { ss[w] = s; ssq[w] = sq; }
    __syncthreads();
    s = 0.f; sq = 0.f;
    #pragma unroll
    for (int i = 0; i < 8; i++) { s += ss[i]; sq += ssq[i]; }

    float mu  = s * (1.0f / DIMC);
    float var = sq * (1.0f / DIMC) - mu * mu;
    float rs  = rsqrtf(var + EPSLN);

    float4 gg = ((const float4*)g)[threadIdx.x];
    float4 bb = ((const float4*)b)[threadIdx.x];
    float4 o;
    o.x = (v.x - mu) * rs * gg.x + bb.x;
    o.y = (v.y - mu) * rs * gg.y + bb.y;
    o.z = (v.z - mu) * rs * gg.z + bb.z;
    o.w = (v.w - mu) * rs * gg.w + bb.w;
    ((float4*)(out + base))[threadIdx.x] = o;
}

// ---------------------------------------------------------------------------
// Spiral conv as chunked linear recurrence: state = p̂*state + p_init*h
// ---------------------------------------------------------------------------
__device__ __forceinline__ void load_phazor(const float* __restrict__ phz, int d,
                                            float& pr, float& pi)
{
    pr = phz[2*d]; pi = phz[2*d+1];
    float pa = sqrtf(pr*pr + pi*pi);
    float sc = expf(-pa) / pa;
    pr *= sc; pi *= sc;
}

// Pass 1: per-(b,chunk,d) partial end-state with zero init.
// grid: BB*NCHUNK*(DIMC/256) blocks, 256 threads
__global__ __launch_bounds__(256) void spiral_pass1(
    const float* __restrict__ h, const float* __restrict__ phz,
    const float* __restrict__ phz_init)
{
    int bc = blockIdx.x >> 2;                       // b*NCHUNK + c
    int d  = ((blockIdx.x & 3) << 8) + threadIdx.x; // 0..1023
    int b  = bc / NCHUNK, c = bc % NCHUNK;

    float pr, pi; load_phazor(phz, d, pr, pi);
    float ir = phz_init[2*d], ii = phz_init[2*d+1];

    float sr = 0.f, si = 0.f;
    const float* hp = h + ((size_t)b*LL + (size_t)c*CHUNK)*DIMC + d;
    #pragma unroll 4
    for (int s = 0; s < CHUNK; s++) {
        float xv = hp[(size_t)s*DIMC];
        float nr = pr*sr - pi*si + ir*xv;
        float ni = pr*si + pi*sr + ii*xv;
        sr = nr; si = ni;
    }
    g_chunkS[(size_t)bc*DIMC + d] = make_float2(sr, si);
}

// Pass 2: serial combine across chunks per (b,d). state[-1] = last.
__global__ void spiral_pass2(
    const float* __restrict__ phz,
    const float* __restrict__ last_re, const float* __restrict__ last_im)
{
    int idx = blockIdx.x * blockDim.x + threadIdx.x;  // BB*DIMC
    if (idx >= BB * DIMC) return;
    int b = idx / DIMC, d = idx % DIMC;

    float pr, pi; load_phazor(phz, d, pr, pi);
    // pC = p̂^CHUNK via 7 squarings (CHUNK=128)
    float cr = pr, ci = pi;
    #pragma unroll
    for (int i = 0; i < 7; i++) {
        float nr = cr*cr - ci*ci;
        ci = 2.f*cr*ci; cr = nr;
    }
    float sr = last_re[idx], si = last_im[idx];
    #pragma unroll
    for (int c = 0; c < NCHUNK; c++) {
        size_t off = ((size_t)b*NCHUNK + c)*DIMC + d;
        g_initS[off] = make_float2(sr, si);
        float2 S = g_chunkS[off];
        float nr = cr*sr - ci*si + S.x;
        float ni = cr*si + ci*sr + S.y;
        sr = nr; si = ni;
    }
}

// Pass 3: recompute within chunk with correct init; y1 = Re(state) + x
__global__ __launch_bounds__(256) void spiral_pass3(
    const float* __restrict__ h, const float* __restrict__ x,
    const float* __restrict__ phz, const float* __restrict__ phz_init)
{
    int bc = blockIdx.x >> 2;
    int d  = ((blockIdx.x & 3) << 8) + threadIdx.x;
    int b  = bc / NCHUNK, c = bc % NCHUNK;

    float pr, pi; load_phazor(phz, d, pr, pi);
    float ir = phz_init[2*d], ii = phz_init[2*d+1];

    float2 st = g_initS[(size_t)bc*DIMC + d];
    float sr = st.x, si = st.y;
    size_t base = ((size_t)b*LL + (size_t)c*CHUNK)*DIMC + d;
    #pragma unroll 2
    for (int s = 0; s < CHUNK; s++) {
        size_t o = base + (size_t)s*DIMC;
        float hv = h[o];
        float nr = pr*sr - pi*si + ir*hv;
        float ni = pr*si + pi*sr + ii*hv;
        sr = nr; si = ni;
        g_y1[o] = sr + x[o];
    }
}

// ---------------------------------------------------------------------------
// SGEMM: C[M,N] = A[M,K] @ B[K,N], 128x128x8 tiles, 256 threads, 8x8/thread
// MODE 0: C = silu(AB + bias);   MODE 1: C = AB + bias + resid
// ---------------------------------------------------------------------------
#define GBM 128
#define GBN 128
#define GBK 8

template<int MODE>
__global__ __launch_bounds__(256) void sgemm_kernel(
    const float* __restrict__ A, const float* __restrict__ B,
    const float* __restrict__ bias, const float* __restrict__ resid,
    float* __restrict__ C, int M, int N, int K)
{
    __shared__ float As[GBK][GBM];
    __shared__ float Bs[GBK][GBN];

    int tid  = threadIdx.x;
    int brow = blockIdx.y * GBM;
    int bcol = blockIdx.x * GBN;
    int tx = tid & 15, ty = tid >> 4;

    float acc[8][8];
    #pragma unroll
    for (int i = 0; i < 8; i++)
        #pragma unroll
        for (int j = 0; j < 8; j++) acc[i][j] = 0.f;

    int arow   = tid >> 1;          // 0..127
    int acol   = (tid & 1) * 4;     // 0 or 4
    int brow_l = tid >> 5;          // 0..7
    int bcol_l = (tid & 31) * 4;    // 0..124

    const float* Ag = A + (size_t)(brow + arow)*K + acol;
    const float* Bg = B + (size_t)brow_l*N + bcol + bcol_l;

    for (int k0 = 0; k0 < K; k0 += GBK) {
        float4 av = *(const float4*)(Ag + k0);
        float4 bv = *(const float4*)(Bg + (size_t)k0*N);
        As[acol+0][arow] = av.x;
        As[acol+1][arow] = av.y;
        As[acol+2][arow] = av.z;
        As[acol+3][arow] = av.w;
        *(float4*)&Bs[brow_l][bcol_l] = bv;
        __syncthreads();

        #pragma unroll
        for (int kk = 0; kk < GBK; kk++) {
            float a[8], bb[8];
            *(float4*)(a)    = *(const float4*)&As[kk][ty*4];
            *(float4*)(a+4)  = *(const float4*)&As[kk][ty*4 + 64];
            *(float4*)(bb)   = *(const float4*)&Bs[kk][tx*4];
            *(float4*)(bb+4) = *(const float4*)&Bs[kk][tx*4 + 64];
            #pragma unroll
            for (int i = 0; i < 8; i++)
                #pragma unroll
                for (int j = 0; j < 8; j++)
                    acc[i][j] = fmaf(a[i], bb[j], acc[i][j]);
        }
        __syncthreads();
    }

    // Epilogue: row(i) = brow + ty*4 + (i&3) + ((i&4)?64:0); col similar with tx
    #pragma unroll
    for (int i = 0; i < 8; i++) {
        int r = brow + ty*4 + (i & 3) + ((i & 4) << 4);
        size_t rowoff = (size_t)r * N;
        #pragma unroll
        for (int jh = 0; jh < 2; jh++) {
            int col = bcol + tx*4 + jh*64;
            float4 bsv = *(const float4*)(bias + col);
            float4 v;
            v.x = acc[i][jh*4+0] + bsv.x;
            v.y = acc[i][jh*4+1] + bsv.y;
            v.z = acc[i][jh*4+2] + bsv.z;
            v.w = acc[i][jh*4+3] + bsv.w;
            if (MODE == 0) {
                v.x = v.x / (1.f + expf(-v.x));
                v.y = v.y / (1.f + expf(-v.y));
                v.z = v.z / (1.f + expf(-v.z));
                v.w = v.w / (1.f + expf(-v.w));
            } else {
                float4 rv = *(const float4*)(resid + rowoff + col);
                v.x += rv.x; v.y += rv.y; v.z += rv.z; v.w += rv.w;
            }
            *(float4*)(C + rowoff + col) = v;
        }
    }
}

// ---------------------------------------------------------------------------
// Launch
// ---------------------------------------------------------------------------
extern "C" void kernel_launch(void* const* d_in, const int* in_sizes, int n_in,
                              void* d_out, int out_size)
{
    (void)in_sizes; (void)n_in; (void)out_size;
    const float* x        = (const float*)d_in[0];
    const float* ln_g     = (const float*)d_in[1];
    const float* ln_b     = (const float*)d_in[2];
    const float* phz      = (const float*)d_in[3];
    const float* phz_init = (const float*)d_in[4];
    const float* w1       = (const float*)d_in[5];
    const float* b1       = (const float*)d_in[6];
    const float* w2       = (const float*)d_in[7];
    const float* b2       = (const float*)d_in[8];
    const float* last_re  = (const float*)d_in[9];
    const float* last_im  = (const float*)d_in[10];
    float* out = (float*)d_out;

    float *h_p, *y1_p, *act_p;
    cudaGetSymbolAddress((void**)&h_p,   g_h);
    cudaGetSymbolAddress((void**)&y1_p,  g_y1);
    cudaGetSymbolAddress((void**)&act_p, g_act);

    // 1) h1 = LN(x)
    ln_kernel<<<MROWS, 256>>>(x, ln_g, ln_b, h_p);

    // 2) spiral conv (chunked scan) + residual -> y1
    spiral_pass1<<<BB*NCHUNK*(DIMC/256), 256>>>(h_p, phz, phz_init);
    spiral_pass2<<<(BB*DIMC + 255)/256, 256>>>(phz, last_re, last_im);
    spiral_pass3<<<BB*NCHUNK*(DIMC/256), 256>>>(h_p, x, phz, phz_init);

    // 3) h2 = LN(y1) (reuse g_h)
    ln_kernel<<<MROWS, 256>>>(y1_p, ln_g, ln_b, h_p);

    // 4) act = silu(h2 @ w1 + b1)
    {
        dim3 grid(DFFC/GBN, MROWS/GBM);
        sgemm_kernel<0><<<grid, 256>>>(h_p, w1, b1, nullptr, act_p,
                                       MROWS, DFFC, DIMC);
    }
    // 5) out = act @ w2 + b2 + y1
    {
        dim3 grid(DIMC/GBN, MROWS/GBM);
        sgemm_kernel<1><<<grid, 256>>>(act_p, w2, b2, y1_p, out,
                                       MROWS, DIMC, DFFC);
    }
}

// round 3
// speedup vs baseline: 3.0647x; 3.0647x over previous
#include <cuda_runtime.h>
#include <math.h>
#include <stdint.h>

// ---------------------------------------------------------------------------
// Problem constants
// ---------------------------------------------------------------------------
#define BB   4
#define LL   2048
#define DIMC 1024
#define DFFC 4096
#define MROWS (BB*LL)        // 8192
#define NCHUNK 16
#define CHUNK  (LL/NCHUNK)   // 128
#define EPSLN 1e-5f

// GEMM tiling (tf32 mma.sync path, base ISA only)
#define BM 128
#define BN 256
#define BKT 16
#define ASTRIDE 20           // BKT + 4 pad (floats) -> conflict-free A frags
#define BSTRIDE 264          // BN + 8 pad (floats)  -> conflict-free B frags
#define A_BYTES (BM*ASTRIDE*4)        // 10240
#define B_BYTES (BKT*BSTRIDE*4)       // 16896
#define STAGE_BYTES (A_BYTES + B_BYTES)   // 27136
#define SMEM_TOT (2*STAGE_BYTES)          // 54272

// ---------------------------------------------------------------------------
// Scratch (device globals: allocation-free rule)
// ---------------------------------------------------------------------------
__device__ float  g_h[(size_t)MROWS*DIMC];
__device__ float  g_y1[(size_t)MROWS*DIMC];
__device__ float  g_act[(size_t)MROWS*DFFC];
__device__ float2 g_chunkS[BB*NCHUNK*DIMC];
__device__ float2 g_initS[BB*NCHUNK*DIMC];

// ---------------------------------------------------------------------------
// PTX helpers (base ISA: cp.async + mma.sync tf32)
// ---------------------------------------------------------------------------
__device__ __forceinline__ void cp16(uint32_t s, const void* gp) {
    asm volatile("cp.async.cg.shared.global [%0], [%1], 16;"
                 :: "r"(s), "l"(gp) : "memory");
}
__device__ __forceinline__ void cp_commit() {
    asm volatile("cp.async.commit_group;" ::: "memory");
}
template<int N> __device__ __forceinline__ void cp_wait() {
    asm volatile("cp.async.wait_group %0;" :: "n"(N) : "memory");
}
__device__ __forceinline__ void mma_tf32(float* d, const uint32_t* a, const uint32_t* b) {
    asm volatile("mma.sync.aligned.m16n8k8.row.col.f32.tf32.tf32.f32 "
                 "{%0,%1,%2,%3}, {%4,%5,%6,%7}, {%8,%9}, {%0,%1,%2,%3};"
                 : "+f"(d[0]), "+f"(d[1]), "+f"(d[2]), "+f"(d[3])
                 : "r"(a[0]), "r"(a[1]), "r"(a[2]), "r"(a[3]),
                   "r"(b[0]), "r"(b[1]));
}

// ---------------------------------------------------------------------------
// LayerNorm: one block per row, 256 threads x 4 floats
// ---------------------------------------------------------------------------
__global__ __launch_bounds__(256) void ln_kernel(
    const float* __restrict__ x, const float* __restrict__ g,
    const float* __restrict__ b, float* __restrict__ out)
{
    int row = blockIdx.x;
    size_t base = (size_t)row * DIMC;
    float4 v = ((const float4*)(x + base))[threadIdx.x];

    float s  = v.x + v.y + v.z + v.w;
    float sq = v.x*v.x + v.y*v.y + v.z*v.z + v.w*v.w;
    #pragma unroll
    for (int o = 16; o > 0; o >>= 1) {
        s  += __shfl_xor_sync(0xffffffffu, s,  o);
        sq += __shfl_xor_sync(0xffffffffu, sq, o);
    }
    __shared__ float ss[8], ssq[8];
    int w = threadIdx.x >> 5, lane = threadIdx.x & 31;
    if (lane == 0) { ss[w] = s; ssq[w] = sq; }
    __syncthreads();
    s = 0.f; sq = 0.f;
    #pragma unroll
    for (int i = 0; i < 8; i++) { s += ss[i]; sq += ssq[i]; }

    float mu  = s * (1.0f / DIMC);
    float var = sq * (1.0f / DIMC) - mu * mu;
    float rs  = rsqrtf(var + EPSLN);

    float4 gg = ((const float4*)g)[threadIdx.x];
    float4 bb = ((const float4*)b)[threadIdx.x];
    float4 o;
    o.x = (v.x - mu) * rs * gg.x + bb.x;
    o.y = (v.y - mu) * rs * gg.y + bb.y;
    o.z = (v.z - mu) * rs * gg.z + bb.z;
    o.w = (v.w - mu) * rs * gg.w + bb.w;
    ((float4*)(out + base))[threadIdx.x] = o;
}

// ---------------------------------------------------------------------------
// Spiral conv as chunked linear recurrence
// ---------------------------------------------------------------------------
__device__ __forceinline__ void load_phazor(const float* __restrict__ phz, int d,
                                            float& pr, float& pi)
{
    pr = phz[2*d]; pi = phz[2*d+1];
    float pa = sqrtf(pr*pr + pi*pi);
    float sc = expf(-pa) / pa;
    pr *= sc; pi *= sc;
}

__global__ __launch_bounds__(256) void spiral_pass1(
    const float* __restrict__ h, const float* __restrict__ phz,
    const float* __restrict__ phz_init)
{
    int bc = blockIdx.x >> 2;
    int d  = ((blockIdx.x & 3) << 8) + threadIdx.x;
    int b  = bc / NCHUNK, c = bc % NCHUNK;

    float pr, pi; load_phazor(phz, d, pr, pi);
    float ir = phz_init[2*d], ii = phz_init[2*d+1];

    float sr = 0.f, si = 0.f;
    const float* hp = h + ((size_t)b*LL + (size_t)c*CHUNK)*DIMC + d;
    #pragma unroll 4
    for (int s = 0; s < CHUNK; s++) {
        float xv = hp[(size_t)s*DIMC];
        float nr = pr*sr - pi*si + ir*xv;
        float ni = pr*si + pi*sr + ii*xv;
        sr = nr; si = ni;
    }
    g_chunkS[(size_t)bc*DIMC + d] = make_float2(sr, si);
}

__global__ void spiral_pass2(
    const float* __restrict__ phz,
    const float* __restrict__ last_re, const float* __restrict__ last_im)
{
    int idx = blockIdx.x * blockDim.x + threadIdx.x;
    if (idx >= BB * DIMC) return;
    int b = idx / DIMC, d = idx % DIMC;

    float pr, pi; load_phazor(phz, d, pr, pi);
    float cr = pr, ci = pi;
    #pragma unroll
    for (int i = 0; i < 7; i++) {
        float nr = cr*cr - ci*ci;
        ci = 2.f*cr*ci; cr = nr;
    }
    float sr = last_re[idx], si = last_im[idx];
    #pragma unroll
    for (int c = 0; c < NCHUNK; c++) {
        size_t off = ((size_t)b*NCHUNK + c)*DIMC + d;
        g_initS[off] = make_float2(sr, si);
        float2 S = g_chunkS[off];
        float nr = cr*sr - ci*si + S.x;
        float ni = cr*si + ci*sr + S.y;
        sr = nr; si = ni;
    }
}

__global__ __launch_bounds__(256) void spiral_pass3(
    const float* __restrict__ h, const float* __restrict__ x,
    const float* __restrict__ phz, const float* __restrict__ phz_init)
{
    int bc = blockIdx.x >> 2;
    int d  = ((blockIdx.x & 3) << 8) + threadIdx.x;
    int b  = bc / NCHUNK, c = bc % NCHUNK;

    float pr, pi; load_phazor(phz, d, pr, pi);
    float ir = phz_init[2*d], ii = phz_init[2*d+1];

    float2 st = g_initS[(size_t)bc*DIMC + d];
    float sr = st.x, si = st.y;
    size_t base = ((size_t)b*LL + (size_t)c*CHUNK)*DIMC + d;
    #pragma unroll 2
    for (int s = 0; s < CHUNK; s++) {
        size_t o = base + (size_t)s*DIMC;
        float hv = h[o];
        float nr = pr*sr - pi*si + ir*hv;
        float ni = pr*si + pi*sr + ii*hv;
        sr = nr; si = ni;
        g_y1[o] = sr + x[o];
    }
}

// ---------------------------------------------------------------------------
// TF32 mma.sync GEMM: C[M,N] = A[M,K] @ B[K,N]  (B row-major [K][N] directly)
// CTA 128x256, BK=16, 8 warps of 64x64, cp.async double buffer.
// MODE 0: C = silu(AB + bias);  MODE 1: C = AB + bias + resid
// ---------------------------------------------------------------------------
template<int MODE>
__global__ __launch_bounds__(256, 1) void mma_gemm(
    const float* __restrict__ A, const float* __restrict__ B,
    const float* __restrict__ bias, const float* __restrict__ resid,
    float* __restrict__ C, int M, int N, int K)
{
    extern __shared__ float dsm[];
    uint32_t sbase = (uint32_t)__cvta_generic_to_shared(dsm);

    int tid  = threadIdx.x;
    int wid  = tid >> 5, lane = tid & 31;
    int g    = lane >> 2, c = lane & 3;
    int wm   = wid >> 2, wn = wid & 3;       // 2 x 4 warps
    int bm   = blockIdx.y * BM;
    int bn   = blockIdx.x * BN;

    float acc[4][8][4];
    #pragma unroll
    for (int mt = 0; mt < 4; mt++)
        #pragma unroll
        for (int nt = 0; nt < 8; nt++)
            #pragma unroll
            for (int i = 0; i < 4; i++) acc[mt][nt][i] = 0.f;

    const float* Abase = A + (size_t)bm * K;
    const float* Bbase = B + bn;

    auto load_tile = [&](int k0, int stage) {
        uint32_t sa = sbase + (uint32_t)stage * STAGE_BYTES;
        uint32_t sb = sa + A_BYTES;
        #pragma unroll
        for (int i = 0; i < 2; i++) {                   // A: 512 x 16B
            int ca = tid + i * 256;
            int row = ca >> 2, q = ca & 3;
            cp16(sa + (uint32_t)row * (ASTRIDE*4) + q * 16,
                 Abase + (size_t)row * K + k0 + q * 4);
        }
        #pragma unroll
        for (int i = 0; i < 4; i++) {                   // B: 1024 x 16B
            int cb = tid + i * 256;
            int kr = cb >> 6, q = cb & 63;
            cp16(sb + (uint32_t)kr * (BSTRIDE*4) + q * 16,
                 Bbase + (size_t)(k0 + kr) * N + q * 4);
        }
        cp_commit();
    };

    int NK = K / BKT;
    load_tile(0, 0);

    for (int k = 0; k < NK; k++) {
        int st = k & 1;
        __syncthreads();                                 // buf st^1 free for reuse
        if (k + 1 < NK) { load_tile((k + 1) * BKT, st ^ 1); cp_wait<1>(); }
        else           { cp_wait<0>(); }
        __syncthreads();                                 // tile k visible

        const float* As = dsm + (size_t)st * (STAGE_BYTES/4);
        const float* Bs = As + BM * ASTRIDE;

        #pragma unroll
        for (int ks = 0; ks < 2; ks++) {
            uint32_t af[4][4], bf[8][2];
            #pragma unroll
            for (int mt = 0; mt < 4; mt++) {
                const float* p = As + (size_t)(wm*64 + mt*16 + g) * ASTRIDE + ks*8 + c;
                af[mt][0] = __float_as_uint(p[0]);
                af[mt][1] = __float_as_uint(p[8*ASTRIDE]);
                af[mt][2] = __float_as_uint(p[4]);
                af[mt][3] = __float_as_uint(p[8*ASTRIDE + 4]);
            }
            #pragma unroll
            for (int nt = 0; nt < 8; nt++) {
                const float* p = Bs + (size_t)(ks*8 + c) * BSTRIDE + wn*64 + nt*8 + g;
                bf[nt][0] = __float_as_uint(p[0]);
                bf[nt][1] = __float_as_uint(p[4*BSTRIDE]);
            }
            #pragma unroll
            for (int mt = 0; mt < 4; mt++)
                #pragma unroll
                for (int nt = 0; nt < 8; nt++)
                    mma_tf32(acc[mt][nt], af[mt], bf[nt]);
        }
    }

    // Epilogue
    #pragma unroll
    for (int mt = 0; mt < 4; mt++) {
        int r0 = bm + wm*64 + mt*16 + g;
        size_t ro0 = (size_t)r0 * N;
        size_t ro1 = (size_t)(r0 + 8) * N;
        #pragma unroll
        for (int nt = 0; nt < 8; nt++) {
            int col = bn + wn*64 + nt*8 + 2*c;
            float2 bs = *(const float2*)(bias + col);
            float2 v0, v1;
            v0.x = acc[mt][nt][0] + bs.x; v0.y = acc[mt][nt][1] + bs.y;
            v1.x = acc[mt][nt][2] + bs.x; v1.y = acc[mt][nt][3] + bs.y;
            if (MODE == 0) {
                v0.x = v0.x / (1.f + __expf(-v0.x));
                v0.y = v0.y / (1.f + __expf(-v0.y));
                v1.x = v1.x / (1.f + __expf(-v1.x));
                v1.y = v1.y / (1.f + __expf(-v1.y));
            } else {
                float2 r0v = *(const float2*)(resid + ro0 + col);
                float2 r1v = *(const float2*)(resid + ro1 + col);
                v0.x += r0v.x; v0.y += r0v.y;
                v1.x += r1v.x; v1.y += r1v.y;
            }
            *(float2*)(C + ro0 + col) = v0;
            *(float2*)(C + ro1 + col) = v1;
        }
    }
}

// ---------------------------------------------------------------------------
// Launch
// ---------------------------------------------------------------------------
extern "C" void kernel_launch(void* const* d_in, const int* in_sizes, int n_in,
                              void* d_out, int out_size)
{
    (void)in_sizes; (void)n_in; (void)out_size;
    const float* x        = (const float*)d_in[0];
    const float* ln_g     = (const float*)d_in[1];
    const float* ln_b     = (const float*)d_in[2];
    const float* phz      = (const float*)d_in[3];
    const float* phz_init = (const float*)d_in[4];
    const float* w1       = (const float*)d_in[5];
    const float* b1       = (const float*)d_in[6];
    const float* w2       = (const float*)d_in[7];
    const float* b2       = (const float*)d_in[8];
    const float* last_re  = (const float*)d_in[9];
    const float* last_im  = (const float*)d_in[10];
    float* out = (float*)d_out;

    float *h_p, *y1_p, *act_p;
    cudaGetSymbolAddress((void**)&h_p,   g_h);
    cudaGetSymbolAddress((void**)&y1_p,  g_y1);
    cudaGetSymbolAddress((void**)&act_p, g_act);

    cudaFuncSetAttribute(mma_gemm<0>, cudaFuncAttributeMaxDynamicSharedMemorySize, SMEM_TOT);
    cudaFuncSetAttribute(mma_gemm<1>, cudaFuncAttributeMaxDynamicSharedMemorySize, SMEM_TOT);

    // 1) h1 = LN(x)
    ln_kernel<<<MROWS, 256>>>(x, ln_g, ln_b, h_p);

    // 2) spiral conv (chunked scan) + residual -> y1
    spiral_pass1<<<BB*NCHUNK*(DIMC/256), 256>>>(h_p, phz, phz_init);
    spiral_pass2<<<(BB*DIMC + 255)/256, 256>>>(phz, last_re, last_im);
    spiral_pass3<<<BB*NCHUNK*(DIMC/256), 256>>>(h_p, x, phz, phz_init);

    // 3) h2 = LN(y1)
    ln_kernel<<<MROWS, 256>>>(y1_p, ln_g, ln_b, h_p);

    // 4) act = silu(h2 @ w1 + b1)   [tf32 mma.sync]
    {
        dim3 grid(DFFC / BN, MROWS / BM);
        mma_gemm<0><<<grid, 256, SMEM_TOT>>>(h_p, w1, b1, nullptr,
                                             act_p, MROWS, DFFC, DIMC);
    }
    // 5) out = act @ w2 + b2 + y1   [tf32 mma.sync]
    {
        dim3 grid(DIMC / BN, MROWS / BM);
        mma_gemm<1><<<grid, 256, SMEM_TOT>>>(act_p, w2, b2, y1_p,
                                             out, MROWS, DIMC, DFFC);
    }
}

// round 4
// speedup vs baseline: 3.1115x; 1.0153x over previous
#include <cuda_runtime.h>
#include <math.h>
#include <stdint.h>

// ---------------------------------------------------------------------------
// Problem constants
// ---------------------------------------------------------------------------
#define BB   4
#define LL   2048
#define DIMC 1024
#define DFFC 4096
#define MROWS (BB*LL)        // 8192
#define NCHUNK 64
#define CHUNK  (LL/NCHUNK)   // 32
#define EPSLN 1e-5f

// GEMM tiling (tf32 mma.sync, base ISA)
#define BM 128
#define BKT 16
#define ASTRIDE 20                       // BKT + 4 pad (floats)
#define A_BYTES (BM*ASTRIDE*4)           // 10240

// ---------------------------------------------------------------------------
// Scratch (device globals: allocation-free rule)
// ---------------------------------------------------------------------------
__device__ float  g_h[(size_t)MROWS*DIMC];
__device__ float  g_y1[(size_t)MROWS*DIMC];
__device__ float  g_act[(size_t)MROWS*DFFC];
__device__ float2 g_chunkS[BB*NCHUNK*DIMC];
__device__ float2 g_initS[BB*NCHUNK*DIMC];

// ---------------------------------------------------------------------------
// PTX helpers (base ISA: cp.async + mma.sync tf32)
// ---------------------------------------------------------------------------
__device__ __forceinline__ void cp16(uint32_t s, const void* gp) {
    asm volatile("cp.async.cg.shared.global [%0], [%1], 16;"
                 :: "r"(s), "l"(gp) : "memory");
}
__device__ __forceinline__ void cp_commit() {
    asm volatile("cp.async.commit_group;" ::: "memory");
}
template<int N> __device__ __forceinline__ void cp_wait() {
    asm volatile("cp.async.wait_group %0;" :: "n"(N) : "memory");
}
__device__ __forceinline__ void mma_tf32(float* d, const uint32_t* a, const uint32_t* b) {
    asm volatile("mma.sync.aligned.m16n8k8.row.col.f32.tf32.tf32.f32 "
                 "{%0,%1,%2,%3}, {%4,%5,%6,%7}, {%8,%9}, {%0,%1,%2,%3};"
                 : "+f"(d[0]), "+f"(d[1]), "+f"(d[2]), "+f"(d[3])
                 : "r"(a[0]), "r"(a[1]), "r"(a[2]), "r"(a[3]),
                   "r"(b[0]), "r"(b[1]));
}

// ---------------------------------------------------------------------------
// LayerNorm: one block per row, 256 threads x 4 floats
// ---------------------------------------------------------------------------
__global__ __launch_bounds__(256) void ln_kernel(
    const float* __restrict__ x, const float* __restrict__ g,
    const float* __restrict__ b, float* __restrict__ out)
{
    int row = blockIdx.x;
    size_t base = (size_t)row * DIMC;
    float4 v = ((const float4*)(x + base))[threadIdx.x];

    float s  = v.x + v.y + v.z + v.w;
    float sq = v.x*v.x + v.y*v.y + v.z*v.z + v.w*v.w;
    #pragma unroll
    for (int o = 16; o > 0; o >>= 1) {
        s  += __shfl_xor_sync(0xffffffffu, s,  o);
        sq += __shfl_xor_sync(0xffffffffu, sq, o);
    }
    __shared__ float ss[8], ssq[8];
    int w = threadIdx.x >> 5, lane = threadIdx.x & 31;
    if (lane == 0) { ss[w] = s; ssq[w] = sq; }
    __syncthreads();
    s = 0.f; sq = 0.f;
    #pragma unroll
    for (int i = 0; i < 8; i++) { s += ss[i]; sq += ssq[i]; }

    float mu  = s * (1.0f / DIMC);
    float var = sq * (1.0f / DIMC) - mu * mu;
    float rs  = rsqrtf(var + EPSLN);

    float4 gg = ((const float4*)g)[threadIdx.x];
    float4 bb = ((const float4*)b)[threadIdx.x];
    float4 o;
    o.x = (v.x - mu) * rs * gg.x + bb.x;
    o.y = (v.y - mu) * rs * gg.y + bb.y;
    o.z = (v.z - mu) * rs * gg.z + bb.z;
    o.w = (v.w - mu) * rs * gg.w + bb.w;
    ((float4*)(out + base))[threadIdx.x] = o;
}

// ---------------------------------------------------------------------------
// Spiral conv as chunked linear recurrence
// ---------------------------------------------------------------------------
__device__ __forceinline__ void load_phazor(const float* __restrict__ phz, int d,
                                            float& pr, float& pi)
{
    pr = phz[2*d]; pi = phz[2*d+1];
    float pa = sqrtf(pr*pr + pi*pi);
    float sc = expf(-pa) / pa;
    pr *= sc; pi *= sc;
}

__global__ __launch_bounds__(256) void spiral_pass1(
    const float* __restrict__ h, const float* __restrict__ phz,
    const float* __restrict__ phz_init)
{
    int bc = blockIdx.x >> 2;
    int d  = ((blockIdx.x & 3) << 8) + threadIdx.x;
    int b  = bc / NCHUNK, c = bc % NCHUNK;

    float pr, pi; load_phazor(phz, d, pr, pi);
    float ir = phz_init[2*d], ii = phz_init[2*d+1];

    float sr = 0.f, si = 0.f;
    const float* hp = h + ((size_t)b*LL + (size_t)c*CHUNK)*DIMC + d;
    #pragma unroll 8
    for (int s = 0; s < CHUNK; s++) {
        float xv = hp[(size_t)s*DIMC];
        float nr = pr*sr - pi*si + ir*xv;
        float ni = pr*si + pi*sr + ii*xv;
        sr = nr; si = ni;
    }
    g_chunkS[(size_t)bc*DIMC + d] = make_float2(sr, si);
}

__global__ void spiral_pass2(
    const float* __restrict__ phz,
    const float* __restrict__ last_re, const float* __restrict__ last_im)
{
    int idx = blockIdx.x * blockDim.x + threadIdx.x;
    if (idx >= BB * DIMC) return;
    int b = idx / DIMC, d = idx % DIMC;

    float pr, pi; load_phazor(phz, d, pr, pi);
    // pC = p̂^CHUNK via 5 squarings (CHUNK=32)
    float cr = pr, ci = pi;
    #pragma unroll
    for (int i = 0; i < 5; i++) {
        float nr = cr*cr - ci*ci;
        ci = 2.f*cr*ci; cr = nr;
    }
    float sr = last_re[idx], si = last_im[idx];
    #pragma unroll 8
    for (int c = 0; c < NCHUNK; c++) {
        size_t off = ((size_t)b*NCHUNK + c)*DIMC + d;
        g_initS[off] = make_float2(sr, si);
        float2 S = g_chunkS[off];
        float nr = cr*sr - ci*si + S.x;
        float ni = cr*si + ci*sr + S.y;
        sr = nr; si = ni;
    }
}

__global__ __launch_bounds__(256) void spiral_pass3(
    const float* __restrict__ h, const float* __restrict__ x,
    const float* __restrict__ phz, const float* __restrict__ phz_init)
{
    int bc = blockIdx.x >> 2;
    int d  = ((blockIdx.x & 3) << 8) + threadIdx.x;
    int b  = bc / NCHUNK, c = bc % NCHUNK;

    float pr, pi; load_phazor(phz, d, pr, pi);
    float ir = phz_init[2*d], ii = phz_init[2*d+1];

    float2 st = g_initS[(size_t)bc*DIMC + d];
    float sr = st.x, si = st.y;
    size_t base = ((size_t)b*LL + (size_t)c*CHUNK)*DIMC + d;
    #pragma unroll 4
    for (int s = 0; s < CHUNK; s++) {
        size_t o = base + (size_t)s*DIMC;
        float hv = h[o];
        float nr = pr*sr - pi*si + ir*hv;
        float ni = pr*si + pi*sr + ii*hv;
        sr = nr; si = ni;
        g_y1[o] = sr + x[o];
    }
}

// ---------------------------------------------------------------------------
// TF32 mma.sync GEMM: C[M,N] = A[M,K] @ B[K,N]  (B row-major [K][N] directly)
// CTA 128xBNT, BK=16, 8 warps (2x4), multistage cp.async circular pipeline.
// MODE 0: C = silu(AB + bias);  MODE 1: C = AB + bias + resid
// ---------------------------------------------------------------------------
template<int MODE, int BNT, int STAGES, int MINCTA>
__global__ __launch_bounds__(256, MINCTA) void mma_gemm(
    const float* __restrict__ A, const float* __restrict__ B,
    const float* __restrict__ bias, const float* __restrict__ resid,
    float* __restrict__ C, int M, int N, int K)
{
    constexpr int BSTR = BNT + 8;                 // B smem stride (floats)
    constexpr int B_BYTES = BKT * BSTR * 4;
    constexpr int STAGE_BYTES = A_BYTES + B_BYTES;
    constexpr int NT = BNT / 4 / 8;               // n-subtiles per warp (8 or 4)
    constexpr int NBCHUNK = (BKT * BNT / 4) / 256;

    extern __shared__ float dsm[];
    uint32_t sbase = (uint32_t)__cvta_generic_to_shared(dsm);

    int tid  = threadIdx.x;
    int wid  = tid >> 5, lane = tid & 31;
    int g    = lane >> 2, c = lane & 3;
    int wm   = wid >> 2, wn = wid & 3;            // 2 x 4 warps
    int bm   = blockIdx.y * BM;
    int bn   = blockIdx.x * BNT;

    float acc[4][NT][4];
    #pragma unroll
    for (int mt = 0; mt < 4; mt++)
        #pragma unroll
        for (int nt = 0; nt < NT; nt++)
            #pragma unroll
            for (int i = 0; i < 4; i++) acc[mt][nt][i] = 0.f;

    const float* Abase = A + (size_t)bm * K;
    const float* Bbase = B + bn;

    auto load_tile = [&](int k0, int stage) {
        uint32_t sa = sbase + (uint32_t)stage * STAGE_BYTES;
        uint32_t sb = sa + A_BYTES;
        #pragma unroll
        for (int i = 0; i < 2; i++) {                         // A: 512 x 16B
            int ca = tid + i * 256;
            int row = ca >> 2, q = ca & 3;
            cp16(sa + (uint32_t)row * (ASTRIDE*4) + q * 16,
                 Abase + (size_t)row * K + k0 + q * 4);
        }
        #pragma unroll
        for (int i = 0; i < NBCHUNK; i++) {                   // B tiles of 16B
            int cb = tid + i * 256;
            int kr = cb / (BNT/4), q = cb % (BNT/4);
            cp16(sb + (uint32_t)kr * (BSTR*4) + q * 16,
                 Bbase + (size_t)(k0 + kr) * N + q * 4);
        }
        cp_commit();
    };

    int NK = K / BKT;
    #pragma unroll
    for (int p = 0; p < STAGES - 1; p++) load_tile(p * BKT, p);

    for (int k = 0; k < NK; k++) {
        cp_wait<STAGES - 2>();          // tile k's data arrived
        __syncthreads();                // visible to all; compute(k-1) finished

        int nk = k + STAGES - 1;
        if (nk < NK) load_tile(nk * BKT, nk % STAGES);
        else         cp_commit();       // empty group keeps wait arithmetic exact

        const float* As = dsm + (size_t)(k % STAGES) * (STAGE_BYTES/4);
        const float* Bs = As + BM * ASTRIDE;

        #pragma unroll
        for (int ks = 0; ks < 2; ks++) {
            uint32_t af[4][4], bf[NT][2];
            #pragma unroll
            for (int mt = 0; mt < 4; mt++) {
                const float* p = As + (size_t)(wm*64 + mt*16 + g) * ASTRIDE + ks*8 + c;
                af[mt][0] = __float_as_uint(p[0]);
                af[mt][1] = __float_as_uint(p[8*ASTRIDE]);
                af[mt][2] = __float_as_uint(p[4]);
                af[mt][3] = __float_as_uint(p[8*ASTRIDE + 4]);
            }
            #pragma unroll
            for (int nt = 0; nt < NT; nt++) {
                const float* p = Bs + (size_t)(ks*8 + c) * BSTR + wn*(NT*8) + nt*8 + g;
                bf[nt][0] = __float_as_uint(p[0]);
                bf[nt][1] = __float_as_uint(p[4*BSTR]);
            }
            #pragma unroll
            for (int mt = 0; mt < 4; mt++)
                #pragma unroll
                for (int nt = 0; nt < NT; nt++)
                    mma_tf32(acc[mt][nt], af[mt], bf[nt]);
        }
    }
    cp_wait<0>();

    // Epilogue
    #pragma unroll
    for (int mt = 0; mt < 4; mt++) {
        int r0 = bm + wm*64 + mt*16 + g;
        size_t ro0 = (size_t)r0 * N;
        size_t ro1 = (size_t)(r0 + 8) * N;
        #pragma unroll
        for (int nt = 0; nt < NT; nt++) {
            int col = bn + wn*(NT*8) + nt*8 + 2*c;
            float2 bs = *(const float2*)(bias + col);
            float2 v0, v1;
            v0.x = acc[mt][nt][0] + bs.x; v0.y = acc[mt][nt][1] + bs.y;
            v1.x = acc[mt][nt][2] + bs.x; v1.y = acc[mt][nt][3] + bs.y;
            if (MODE == 0) {
                v0.x = v0.x / (1.f + __expf(-v0.x));
                v0.y = v0.y / (1.f + __expf(-v0.y));
                v1.x = v1.x / (1.f + __expf(-v1.x));
                v1.y = v1.y / (1.f + __expf(-v1.y));
            } else {
                float2 r0v = *(const float2*)(resid + ro0 + col);
                float2 r1v = *(const float2*)(resid + ro1 + col);
                v0.x += r0v.x; v0.y += r0v.y;
                v1.x += r1v.x; v1.y += r1v.y;
            }
            *(float2*)(C + ro0 + col) = v0;
            *(float2*)(C + ro1 + col) = v1;
        }
    }
}

// Instantiation configs
#define G1_STAGES 4
#define G1_SMEM ((A_BYTES + BKT*(256+8)*4) * G1_STAGES)   // 108544
#define G2_STAGES 3
#define G2_SMEM ((A_BYTES + BKT*(128+8)*4) * G2_STAGES)   // 56832

// ---------------------------------------------------------------------------
// Launch
// ---------------------------------------------------------------------------
extern "C" void kernel_launch(void* const* d_in, const int* in_sizes, int n_in,
                              void* d_out, int out_size)
{
    (void)in_sizes; (void)n_in; (void)out_size;
    const float* x        = (const float*)d_in[0];
    const float* ln_g     = (const float*)d_in[1];
    const float* ln_b     = (const float*)d_in[2];
    const float* phz      = (const float*)d_in[3];
    const float* phz_init = (const float*)d_in[4];
    const float* w1       = (const float*)d_in[5];
    const float* b1       = (const float*)d_in[6];
    const float* w2       = (const float*)d_in[7];
    const float* b2       = (const float*)d_in[8];
    const float* last_re  = (const float*)d_in[9];
    const float* last_im  = (const float*)d_in[10];
    float* out = (float*)d_out;

    float *h_p, *y1_p, *act_p;
    cudaGetSymbolAddress((void**)&h_p,   g_h);
    cudaGetSymbolAddress((void**)&y1_p,  g_y1);
    cudaGetSymbolAddress((void**)&act_p, g_act);

    cudaFuncSetAttribute((const void*)mma_gemm<0,256,G1_STAGES,1>,
                         cudaFuncAttributeMaxDynamicSharedMemorySize, G1_SMEM);
    cudaFuncSetAttribute((const void*)mma_gemm<1,128,G2_STAGES,2>,
                         cudaFuncAttributeMaxDynamicSharedMemorySize, G2_SMEM);

    // 1) h1 = LN(x)
    ln_kernel<<<MROWS, 256>>>(x, ln_g, ln_b, h_p);

    // 2) spiral conv (chunked scan) + residual -> y1
    spiral_pass1<<<BB*NCHUNK*(DIMC/256), 256>>>(h_p, phz, phz_init);
    spiral_pass2<<<(BB*DIMC + 255)/256, 256>>>(phz, last_re, last_im);
    spiral_pass3<<<BB*NCHUNK*(DIMC/256), 256>>>(h_p, x, phz, phz_init);

    // 3) h2 = LN(y1)
    ln_kernel<<<MROWS, 256>>>(y1_p, ln_g, ln_b, h_p);

    // 4) act = silu(h2 @ w1 + b1)   [tf32 mma.sync, 128x256, 4-stage]
    {
        dim3 grid(DFFC / 256, MROWS / BM);
        mma_gemm<0,256,G1_STAGES,1><<<grid, 256, G1_SMEM>>>(
            h_p, w1, b1, nullptr, act_p, MROWS, DFFC, DIMC);
    }
    // 5) out = act @ w2 + b2 + y1   [tf32 mma.sync, 128x128, 3-stage, 2 CTA/SM]
    {
        dim3 grid(DIMC / 128, MROWS / BM);
        mma_gemm<1,128,G2_STAGES,2><<<grid, 256, G2_SMEM>>>(
            act_p, w2, b2, y1_p, out, MROWS, DIMC, DFFC);
    }
}

// round 6
// speedup vs baseline: 4.8356x; 1.5541x over previous
#include <cuda_runtime.h>
#include <cuda_fp16.h>
#include <math.h>
#include <stdint.h>

// ---------------------------------------------------------------------------
// Problem constants
// ---------------------------------------------------------------------------
#define BB   4
#define LL   2048
#define DIMC 1024
#define DFFC 4096
#define MROWS (BB*LL)        // 8192
#define NCHUNK 64
#define CHUNK  (LL/NCHUNK)   // 32
#define EPSLN 1e-5f

// GEMM tiling (fp16 mma.sync m16n8k16, fp32 accumulate)
#define BM 128
#define BKT 32               // K per stage (halves)
#define ASTRH 40             // smem row stride in halves (80B)

// ---------------------------------------------------------------------------
// Scratch (device globals: allocation-free rule)
// ---------------------------------------------------------------------------
__device__ float  g_h[(size_t)MROWS*DIMC];       // LN1 out (f32, spiral input)
__device__ float  g_y1[(size_t)MROWS*DIMC];      // conv + x residual (f32)
__device__ __half g_h16[(size_t)MROWS*DIMC];     // LN2 out (fp16, GEMM1 A)
__device__ __half g_act16[(size_t)MROWS*DFFC];   // silu FFN mid (fp16, GEMM2 A)
__device__ __half g_w1t[(size_t)DFFC*DIMC];      // w1^T fp16 [DFF][DIM]
__device__ __half g_w2t[(size_t)DIMC*DFFC];      // w2^T fp16 [DIM][DFF]
__device__ float2 g_chunkS[BB*NCHUNK*DIMC];
__device__ float2 g_initS[BB*NCHUNK*DIMC];

// ---------------------------------------------------------------------------
// PTX helpers (base ISA: cp.async + mma.sync fp16)
// ---------------------------------------------------------------------------
__device__ __forceinline__ void cp16(uint32_t s, const void* gp) {
    asm volatile("cp.async.cg.shared.global [%0], [%1], 16;"
                 :: "r"(s), "l"(gp) : "memory");
}
__device__ __forceinline__ void cp_commit() {
    asm volatile("cp.async.commit_group;" ::: "memory");
}
template<int N> __device__ __forceinline__ void cp_wait() {
    asm volatile("cp.async.wait_group %0;" :: "n"(N) : "memory");
}
__device__ __forceinline__ void mma_f16(float* d, const uint32_t* a, const uint32_t* b) {
    asm volatile("mma.sync.aligned.m16n8k16.row.col.f32.f16.f16.f32 "
                 "{%0,%1,%2,%3}, {%4,%5,%6,%7}, {%8,%9}, {%0,%1,%2,%3};"
                 : "+f"(d[0]), "+f"(d[1]), "+f"(d[2]), "+f"(d[3])
                 : "r"(a[0]), "r"(a[1]), "r"(a[2]), "r"(a[3]),
                   "r"(b[0]), "r"(b[1]));
}

// ---------------------------------------------------------------------------
// LayerNorm: one block per row, 256 threads x 4 floats. HOUT: 0=f32, 1=fp16
// ---------------------------------------------------------------------------
template<int HOUT>
__global__ __launch_bounds__(256) void ln_kernel(
    const float* __restrict__ x, const float* __restrict__ g,
    const float* __restrict__ b, void* __restrict__ outv)
{
    int row = blockIdx.x;
    size_t base = (size_t)row * DIMC;
    float4 v = ((const float4*)(x + base))[threadIdx.x];

    float s  = v.x + v.y + v.z + v.w;
    float sq = v.x*v.x + v.y*v.y + v.z*v.z + v.w*v.w;
    #pragma unroll
    for (int o = 16; o > 0; o >>= 1) {
        s  += __shfl_xor_sync(0xffffffffu, s,  o);
        sq += __shfl_xor_sync(0xffffffffu, sq, o);
    }
    __shared__ float ss[8], ssq[8];
    int w = threadIdx.x >> 5, lane = threadIdx.x & 31;
    if (lane == 0) { ss[w] = s; ssq[w] = sq; }
    __syncthreads();
    s = 0.f; sq = 0.f;
    #pragma unroll
    for (int i = 0; i < 8; i++) { s += ss[i]; sq += ssq[i]; }

    float mu  = s * (1.0f / DIMC);
    float var = sq * (1.0f / DIMC) - mu * mu;
    float rs  = rsqrtf(var + EPSLN);

    float4 gg = ((const float4*)g)[threadIdx.x];
    float4 bb = ((const float4*)b)[threadIdx.x];
    float4 o;
    o.x = (v.x - mu) * rs * gg.x + bb.x;
    o.y = (v.y - mu) * rs * gg.y + bb.y;
    o.z = (v.z - mu) * rs * gg.z + bb.z;
    o.w = (v.w - mu) * rs * gg.w + bb.w;
    if (HOUT) {
        __half2* oh = (__half2*)((__half*)outv + base);
        oh[threadIdx.x * 2 + 0] = __floats2half2_rn(o.x, o.y);
        oh[threadIdx.x * 2 + 1] = __floats2half2_rn(o.z, o.w);
    } else {
        ((float4*)((float*)outv + base))[threadIdx.x] = o;
    }
}

// ---------------------------------------------------------------------------
// Spiral conv as chunked linear recurrence
// ---------------------------------------------------------------------------
__device__ __forceinline__ void load_phazor(const float* __restrict__ phz, int d,
                                            float& pr, float& pi)
{
    pr = phz[2*d]; pi = phz[2*d+1];
    float pa = sqrtf(pr*pr + pi*pi);
    float sc = expf(-pa) / pa;
    pr *= sc; pi *= sc;
}

__global__ __launch_bounds__(256) void spiral_pass1(
    const float* __restrict__ h, const float* __restrict__ phz,
    const float* __restrict__ phz_init)
{
    int bc = blockIdx.x >> 2;
    int d  = ((blockIdx.x & 3) << 8) + threadIdx.x;
    int b  = bc / NCHUNK, c = bc % NCHUNK;

    float pr, pi; load_phazor(phz, d, pr, pi);
    float ir = phz_init[2*d], ii = phz_init[2*d+1];

    float sr = 0.f, si = 0.f;
    const float* hp = h + ((size_t)b*LL + (size_t)c*CHUNK)*DIMC + d;
    #pragma unroll 8
    for (int s = 0; s < CHUNK; s++) {
        float xv = hp[(size_t)s*DIMC];
        float nr = pr*sr - pi*si + ir*xv;
        float ni = pr*si + pi*sr + ii*xv;
        sr = nr; si = ni;
    }
    g_chunkS[(size_t)bc*DIMC + d] = make_float2(sr, si);
}

__global__ void spiral_pass2(
    const float* __restrict__ phz,
    const float* __restrict__ last_re, const float* __restrict__ last_im)
{
    int idx = blockIdx.x * blockDim.x + threadIdx.x;
    if (idx >= BB * DIMC) return;
    int b = idx / DIMC, d = idx % DIMC;

    float pr, pi; load_phazor(phz, d, pr, pi);
    float cr = pr, ci = pi;               // p̂^CHUNK via 5 squarings (CHUNK=32)
    #pragma unroll
    for (int i = 0; i < 5; i++) {
        float nr = cr*cr - ci*ci;
        ci = 2.f*cr*ci; cr = nr;
    }
    float sr = last_re[idx], si = last_im[idx];
    #pragma unroll 8
    for (int c = 0; c < NCHUNK; c++) {
        size_t off = ((size_t)b*NCHUNK + c)*DIMC + d;
        g_initS[off] = make_float2(sr, si);
        float2 S = g_chunkS[off];
        float nr = cr*sr - ci*si + S.x;
        float ni = cr*si + ci*sr + S.y;
        sr = nr; si = ni;
    }
}

__global__ __launch_bounds__(256) void spiral_pass3(
    const float* __restrict__ h, const float* __restrict__ x,
    const float* __restrict__ phz, const float* __restrict__ phz_init)
{
    int bc = blockIdx.x >> 2;
    int d  = ((blockIdx.x & 3) << 8) + threadIdx.x;
    int b  = bc / NCHUNK, c = bc % NCHUNK;

    float pr, pi; load_phazor(phz, d, pr, pi);
    float ir = phz_init[2*d], ii = phz_init[2*d+1];

    float2 st = g_initS[(size_t)bc*DIMC + d];
    float sr = st.x, si = st.y;
    size_t base = ((size_t)b*LL + (size_t)c*CHUNK)*DIMC + d;
    #pragma unroll 4
    for (int s = 0; s < CHUNK; s++) {
        size_t o = base + (size_t)s*DIMC;
        float hv = h[o];
        float nr = pr*sr - pi*si + ir*hv;
        float ni = pr*si + pi*sr + ii*hv;
        sr = nr; si = ni;
        g_y1[o] = sr + x[o];
    }
}

// ---------------------------------------------------------------------------
// Transpose + convert: in f32 [R][C] -> out fp16 [C][R]
// ---------------------------------------------------------------------------
__global__ __launch_bounds__(256) void convT_kernel(
    const float* __restrict__ in, __half* __restrict__ out, int R, int C)
{
    __shared__ float t[32][33];
    int bx = blockIdx.x * 32, by = blockIdx.y * 32;
    int x = threadIdx.x, y = threadIdx.y;
    #pragma unroll
    for (int i = 0; i < 32; i += 8)
        t[y + i][x] = in[(size_t)(by + y + i) * C + bx + x];
    __syncthreads();
    #pragma unroll
    for (int i = 0; i < 32; i += 8)
        out[(size_t)(bx + y + i) * R + by + x] = __float2half(t[x][y + i]);
}

// ---------------------------------------------------------------------------
// FP16 mma.sync GEMM: C[M,N] = A[M,K] @ Bt[N,K]^T, A/Bt fp16 K-major.
// CTA 128xBNT, BK=32 (2 x k16), 8 warps (2x4), multistage cp.async pipeline.
// MODE 0: C = fp16( silu(AB + bias) );  MODE 1: C = f32( AB + bias + resid )
// ---------------------------------------------------------------------------
template<int MODE, int BNT, int STAGES, int MINCTA>
__global__ __launch_bounds__(256, MINCTA) void mma_gemm(
    const __half* __restrict__ A, const __half* __restrict__ Bt,
    const float* __restrict__ bias, const float* __restrict__ resid,
    void* __restrict__ Cv, int M, int N, int K)
{
    constexpr int NT = BNT / 4 / 8;                   // n-subtiles/warp (8 or 4)
    constexpr int STAGE_BYTES = (BM + BNT) * ASTRH * 2;
    constexpr int A_HALVES = BM * ASTRH;
    constexpr int NB_ITERS = (BNT * 4) / 256;         // B 16B-chunks / 256 thr

    extern __shared__ char dsm[];
    uint32_t sbase = (uint32_t)__cvta_generic_to_shared(dsm);

    int tid  = threadIdx.x;
    int wid  = tid >> 5, lane = tid & 31;
    int g    = lane >> 2, c = lane & 3;
    int wm   = wid >> 2, wn = wid & 3;                // 2 x 4 warps
    int bm   = blockIdx.y * BM;
    int bn   = blockIdx.x * BNT;

    float acc[4][NT][4];
    #pragma unroll
    for (int mt = 0; mt < 4; mt++)
        #pragma unroll
        for (int nt = 0; nt < NT; nt++)
            #pragma unroll
            for (int i = 0; i < 4; i++) acc[mt][nt][i] = 0.f;

    const __half* Abase = A  + (size_t)bm * K;
    const __half* Bbase = Bt + (size_t)bn * K;

    int arow = tid >> 2, aq = tid & 3;                // 16B chunk coords

    auto load_tile = [&](int k0, int stage) {
        uint32_t sa = sbase + (uint32_t)stage * STAGE_BYTES;
        uint32_t sb = sa + A_HALVES * 2;
        #pragma unroll
        for (int i = 0; i < 2; i++) {                 // A: 512 chunks
            int row = arow + i * 64;
            cp16(sa + (uint32_t)row * (ASTRH*2) + aq * 16,
                 Abase + (size_t)row * K + k0 + aq * 8);
        }
        #pragma unroll
        for (int i = 0; i < NB_ITERS; i++) {          // B: BNT*4 chunks
            int row = arow + i * 64;
            cp16(sb + (uint32_t)row * (ASTRH*2) + aq * 16,
                 Bbase + (size_t)row * K + k0 + aq * 8);
        }
        cp_commit();
    };

    int NK = K / BKT;
    #pragma unroll
    for (int p = 0; p < STAGES - 1; p++) load_tile(p * BKT, p);

    for (int k = 0; k < NK; k++) {
        cp_wait<STAGES - 2>();
        __syncthreads();

        int nk = k + STAGES - 1;
        if (nk < NK) load_tile(nk * BKT, nk % STAGES);
        else         cp_commit();                     // keep wait counts exact

        const __half* As = (const __half*)(dsm + (size_t)(k % STAGES) * STAGE_BYTES);
        const __half* Bs = As + A_HALVES;

        #pragma unroll
        for (int ks = 0; ks < 2; ks++) {
            uint32_t af[4][4], bf[NT][2];
            #pragma unroll
            for (int mt = 0; mt < 4; mt++) {
                const __half* p = As + (size_t)(wm*64 + mt*16 + g) * ASTRH + ks*16 + 2*c;
                af[mt][0] = *(const uint32_t*)(p);
                af[mt][1] = *(const uint32_t*)(p + 8*ASTRH);
                af[mt][2] = *(const uint32_t*)(p + 8);
                af[mt][3] = *(const uint32_t*)(p + 8*ASTRH + 8);
            }
            #pragma unroll
            for (int nt = 0; nt < NT; nt++) {
                const __half* p = Bs + (size_t)(wn*(NT*8) + nt*8 + g) * ASTRH + ks*16 + 2*c;
                bf[nt][0] = *(const uint32_t*)(p);
                bf[nt][1] = *(const uint32_t*)(p + 8);
            }
            #pragma unroll
            for (int mt = 0; mt < 4; mt++)
                #pragma unroll
                for (int nt = 0; nt < NT; nt++)
                    mma_f16(acc[mt][nt], af[mt], bf[nt]);
        }
    }
    cp_wait<0>();

    // Epilogue: D fragment rows (r0, r0+8), cols (col, col+1)
    #pragma unroll
    for (int mt = 0; mt < 4; mt++) {
        int r0 = bm + wm*64 + mt*16 + g;
        size_t ro0 = (size_t)r0 * N;
        size_t ro1 = (size_t)(r0 + 8) * N;
        #pragma unroll
        for (int nt = 0; nt < NT; nt++) {
            int col = bn + wn*(NT*8) + nt*8 + 2*c;
            float2 bs = *(const float2*)(bias + col);
            float v0 = acc[mt][nt][0] + bs.x, v1 = acc[mt][nt][1] + bs.y;
            float v2 = acc[mt][nt][2] + bs.x, v3 = acc[mt][nt][3] + bs.y;
            if (MODE == 0) {
                v0 = v0 / (1.f + __expf(-v0));
                v1 = v1 / (1.f + __expf(-v1));
                v2 = v2 / (1.f + __expf(-v2));
                v3 = v3 / (1.f + __expf(-v3));
                __half* C16 = (__half*)Cv;
                *(__half2*)(C16 + ro0 + col) = __floats2half2_rn(v0, v1);
                *(__half2*)(C16 + ro1 + col) = __floats2half2_rn(v2, v3);
            } else {
                float* C = (float*)Cv;
                float2 r0v = *(const float2*)(resid + ro0 + col);
                float2 r1v = *(const float2*)(resid + ro1 + col);
                float2 o0 = make_float2(v0 + r0v.x, v1 + r0v.y);
                float2 o1 = make_float2(v2 + r1v.x, v3 + r1v.y);
                *(float2*)(C + ro0 + col) = o0;
                *(float2*)(C + ro1 + col) = o1;
            }
        }
    }
}

// Instantiation configs
#define G1_STAGES 4
#define G1_SMEM ((BM + 256) * ASTRH * 2 * G1_STAGES)  // 122880
#define G2_STAGES 3
#define G2_SMEM ((BM + 128) * ASTRH * 2 * G2_STAGES)  // 61440 (x2 CTA = 122880)

// ---------------------------------------------------------------------------
// Launch
// ---------------------------------------------------------------------------
extern "C" void kernel_launch(void* const* d_in, const int* in_sizes, int n_in,
                              void* d_out, int out_size)
{
    (void)in_sizes; (void)n_in; (void)out_size;
    const float* x        = (const float*)d_in[0];
    const float* ln_g     = (const float*)d_in[1];
    const float* ln_b     = (const float*)d_in[2];
    const float* phz      = (const float*)d_in[3];
    const float* phz_init = (const float*)d_in[4];
    const float* w1       = (const float*)d_in[5];
    const float* b1       = (const float*)d_in[6];
    const float* w2       = (const float*)d_in[7];
    const float* b2       = (const float*)d_in[8];
    const float* last_re  = (const float*)d_in[9];
    const float* last_im  = (const float*)d_in[10];
    float* out = (float*)d_out;

    float  *h_p, *y1_p;
    __half *h16_p, *act_p, *w1t_p, *w2t_p;
    cudaGetSymbolAddress((void**)&h_p,   g_h);
    cudaGetSymbolAddress((void**)&y1_p,  g_y1);
    cudaGetSymbolAddress((void**)&h16_p, g_h16);
    cudaGetSymbolAddress((void**)&act_p, g_act16);
    cudaGetSymbolAddress((void**)&w1t_p, g_w1t);
    cudaGetSymbolAddress((void**)&w2t_p, g_w2t);

    cudaFuncSetAttribute((const void*)mma_gemm<0,256,G1_STAGES,1>,
                         cudaFuncAttributeMaxDynamicSharedMemorySize, G1_SMEM);
    cudaFuncSetAttribute((const void*)mma_gemm<1,128,G2_STAGES,2>,
                         cudaFuncAttributeMaxDynamicSharedMemorySize, G2_SMEM);

    // 0) weights -> K-major fp16
    {
        dim3 blk(32, 8);
        convT_kernel<<<dim3(DFFC/32, DIMC/32), blk>>>(w1, w1t_p, DIMC, DFFC);
        convT_kernel<<<dim3(DIMC/32, DFFC/32), blk>>>(w2, w2t_p, DFFC, DIMC);
    }

    // 1) h1 = LN(x)  (f32 for spiral)
    ln_kernel<0><<<MROWS, 256>>>(x, ln_g, ln_b, h_p);

    // 2) spiral conv (chunked scan) + residual -> y1
    spiral_pass1<<<BB*NCHUNK*(DIMC/256), 256>>>(h_p, phz, phz_init);
    spiral_pass2<<<(BB*DIMC + 255)/256, 256>>>(phz, last_re, last_im);
    spiral_pass3<<<BB*NCHUNK*(DIMC/256), 256>>>(h_p, x, phz, phz_init);

    // 3) h2 = LN(y1)  (fp16 for GEMM1)
    ln_kernel<1><<<MROWS, 256>>>(y1_p, ln_g, ln_b, h16_p);

    // 4) act16 = fp16(silu(h2 @ w1 + b1))   [fp16 mma.sync, 128x256, 4-stage]
    {
        dim3 grid(DFFC / 256, MROWS / BM);
        mma_gemm<0,256,G1_STAGES,1><<<grid, 256, G1_SMEM>>>(
            h16_p, w1t_p, b1, nullptr, act_p, MROWS, DFFC, DIMC);
    }
    // 5) out = act16 @ w2 + b2 + y1   [fp16 mma.sync, 128x128, 3-stage, 2 CTA/SM]
    {
        dim3 grid(DIMC / 128, MROWS / BM);
        mma_gemm<1,128,G2_STAGES,2><<<grid, 256, G2_SMEM>>>(
            act_p, w2t_p, b2, y1_p, out, MROWS, DIMC, DFFC);
    }
}

// round 8
// speedup vs baseline: 5.1983x; 1.0750x over previous
#include <cuda_runtime.h>
#include <cuda_fp16.h>
#include <math.h>
#include <stdint.h>

// ---------------------------------------------------------------------------
// Problem constants
// ---------------------------------------------------------------------------
#define BB   4
#define LL   2048
#define DIMC 1024
#define DFFC 4096
#define MROWS (BB*LL)        // 8192
#define NCHUNK 64
#define CHUNK  (LL/NCHUNK)   // 32
#define EPSLN 1e-5f

// GEMM tiling (fp16 mma.sync m16n8k16, fp32 accumulate)
#define BM 128
#define BNT 128
#define BKT 32               // halves of K per stage
#define ASTRH 40             // smem row stride in halves (80B) -> conflict-free
#define STAGES 3
#define STAGE_BYTES ((BM + BNT) * ASTRH * 2)     // 20480
#define GSMEM (STAGES * STAGE_BYTES)             // 61440 (x2 CTA/SM = 122880)
#define A_SMEM_BYTES (BM * ASTRH * 2)

// ---------------------------------------------------------------------------
// Scratch (device globals: allocation-free rule)
// ---------------------------------------------------------------------------
__device__ float  g_y1[(size_t)MROWS*DIMC];      // conv + x residual (f32)
__device__ __half g_h16[(size_t)MROWS*DIMC];     // LN2 out (fp16, GEMM1 A)
__device__ __half g_act16[(size_t)MROWS*DFFC];   // silu FFN mid (fp16, GEMM2 A)
__device__ __half g_w1t[(size_t)DFFC*DIMC];      // w1^T fp16 [DFF][DIM]
__device__ __half g_w2t[(size_t)DIMC*DFFC];      // w2^T fp16 [DIM][DFF]
__device__ float2 g_stat[MROWS];                 // LN1 (mu, rsqrt) per row
__device__ float2 g_chunkS[BB*NCHUNK*DIMC];
__device__ float2 g_initS[BB*NCHUNK*DIMC];

// ---------------------------------------------------------------------------
// PTX helpers (base ISA: cp.async + ldmatrix + mma.sync fp16)
// ---------------------------------------------------------------------------
__device__ __forceinline__ void cp16(uint32_t s, const void* gp) {
    asm volatile("cp.async.cg.shared.global [%0], [%1], 16;"
                 :: "r"(s), "l"(gp) : "memory");
}
__device__ __forceinline__ void cp_commit() {
    asm volatile("cp.async.commit_group;" ::: "memory");
}
template<int N> __device__ __forceinline__ void cp_wait() {
    asm volatile("cp.async.wait_group %0;" :: "n"(N) : "memory");
}
__device__ __forceinline__ void ldsm_x4(uint32_t& r0, uint32_t& r1,
                                        uint32_t& r2, uint32_t& r3, uint32_t a) {
    asm volatile("ldmatrix.sync.aligned.m8n8.x4.shared.b16 {%0,%1,%2,%3}, [%4];"
                 : "=r"(r0), "=r"(r1), "=r"(r2), "=r"(r3) : "r"(a));
}
__device__ __forceinline__ void mma_f16(float* d, const uint32_t* a, const uint32_t* b) {
    asm volatile("mma.sync.aligned.m16n8k16.row.col.f32.f16.f16.f32 "
                 "{%0,%1,%2,%3}, {%4,%5,%6,%7}, {%8,%9}, {%0,%1,%2,%3};"
                 : "+f"(d[0]), "+f"(d[1]), "+f"(d[2]), "+f"(d[3])
                 : "r"(a[0]), "r"(a[1]), "r"(a[2]), "r"(a[3]),
                   "r"(b[0]), "r"(b[1]));
}

// ---------------------------------------------------------------------------
// Row reduction helper (256 threads, D=1024 as float4)
// ---------------------------------------------------------------------------
__device__ __forceinline__ void row_stats(float4 v, float& mu, float& rs) {
    float s  = v.x + v.y + v.z + v.w;
    float sq = v.x*v.x + v.y*v.y + v.z*v.z + v.w*v.w;
    #pragma unroll
    for (int o = 16; o > 0; o >>= 1) {
        s  += __shfl_xor_sync(0xffffffffu, s,  o);
        sq += __shfl_xor_sync(0xffffffffu, sq, o);
    }
    __shared__ float ss[8], ssq[8];
    int w = threadIdx.x >> 5, lane = threadIdx.x & 31;
    if (lane == 0) { ss[w] = s; ssq[w] = sq; }
    __syncthreads();
    s = 0.f; sq = 0.f;
    #pragma unroll
    for (int i = 0; i < 8; i++) { s += ss[i]; sq += ssq[i]; }
    mu = s * (1.0f / DIMC);
    float var = sq * (1.0f / DIMC) - mu * mu;
    rs = rsqrtf(var + EPSLN);
}

// LN1 stats only: (mu, rs) per row of x
__global__ __launch_bounds__(256) void rowstats_kernel(
    const float* __restrict__ x, float2* __restrict__ stat)
{
    int row = blockIdx.x;
    float4 v = ((const float4*)(x + (size_t)row * DIMC))[threadIdx.x];
    float mu, rs; row_stats(v, mu, rs);
    if (threadIdx.x == 0) stat[row] = make_float2(mu, rs);
}

// LN2: full layernorm of y1 -> fp16
__global__ __launch_bounds__(256) void ln2_kernel(
    const float* __restrict__ x, const float* __restrict__ g,
    const float* __restrict__ b, __half* __restrict__ out)
{
    int row = blockIdx.x;
    size_t base = (size_t)row * DIMC;
    float4 v = ((const float4*)(x + base))[threadIdx.x];
    float mu, rs; row_stats(v, mu, rs);

    float4 gg = ((const float4*)g)[threadIdx.x];
    float4 bb = ((const float4*)b)[threadIdx.x];
    float ox = (v.x - mu) * rs * gg.x + bb.x;
    float oy = (v.y - mu) * rs * gg.y + bb.y;
    float oz = (v.z - mu) * rs * gg.z + bb.z;
    float ow = (v.w - mu) * rs * gg.w + bb.w;
    __half2* oh = (__half2*)(out + base);
    oh[threadIdx.x * 2 + 0] = __floats2half2_rn(ox, oy);
    oh[threadIdx.x * 2 + 1] = __floats2half2_rn(oz, ow);
}

// ---------------------------------------------------------------------------
// Spiral conv as chunked linear recurrence (LN1 fused via g_stat)
// ---------------------------------------------------------------------------
__device__ __forceinline__ void load_phazor(const float* __restrict__ phz, int d,
                                            float& pr, float& pi)
{
    pr = phz[2*d]; pi = phz[2*d+1];
    float pa = sqrtf(pr*pr + pi*pi);
    float sc = expf(-pa) / pa;
    pr *= sc; pi *= sc;
}

__global__ __launch_bounds__(256) void spiral_pass1(
    const float* __restrict__ x, const float* __restrict__ phz,
    const float* __restrict__ phz_init,
    const float* __restrict__ lng, const float* __restrict__ lnb)
{
    int bc = blockIdx.x >> 2;
    int d  = ((blockIdx.x & 3) << 8) + threadIdx.x;
    int b  = bc / NCHUNK, c = bc % NCHUNK;

    float pr, pi; load_phazor(phz, d, pr, pi);
    float ir = phz_init[2*d], ii = phz_init[2*d+1];
    float gg = lng[d], bb2 = lnb[d];

    int row0 = b*LL + c*CHUNK;
    const float*  xp  = x + (size_t)row0 * DIMC + d;
    const float2* stp = g_stat + row0;

    float sr = 0.f, si = 0.f;
    #pragma unroll 8
    for (int s = 0; s < CHUNK; s++) {
        float2 st = stp[s];
        float hv = (xp[(size_t)s*DIMC] - st.x) * st.y * gg + bb2;
        float nr = pr*sr - pi*si + ir*hv;
        float ni = pr*si + pi*sr + ii*hv;
        sr = nr; si = ni;
    }
    g_chunkS[(size_t)bc*DIMC + d] = make_float2(sr, si);
}

__global__ void spiral_pass2(
    const float* __restrict__ phz,
    const float* __restrict__ last_re, const float* __restrict__ last_im)
{
    int idx = blockIdx.x * blockDim.x + threadIdx.x;
    if (idx >= BB * DIMC) return;
    int b = idx / DIMC, d = idx % DIMC;

    float pr, pi; load_phazor(phz, d, pr, pi);
    float cr = pr, ci = pi;               // p̂^CHUNK via 5 squarings (CHUNK=32)
    #pragma unroll
    for (int i = 0; i < 5; i++) {
        float nr = cr*cr - ci*ci;
        ci = 2.f*cr*ci; cr = nr;
    }
    float sr = last_re[idx], si = last_im[idx];
    #pragma unroll 8
    for (int c = 0; c < NCHUNK; c++) {
        size_t off = ((size_t)b*NCHUNK + c)*DIMC + d;
        g_initS[off] = make_float2(sr, si);
        float2 S = g_chunkS[off];
        float nr = cr*sr - ci*si + S.x;
        float ni = cr*si + ci*sr + S.y;
        sr = nr; si = ni;
    }
}

__global__ __launch_bounds__(256) void spiral_pass3(
    const float* __restrict__ x, const float* __restrict__ phz,
    const float* __restrict__ phz_init,
    const float* __restrict__ lng, const float* __restrict__ lnb)
{
    int bc = blockIdx.x >> 2;
    int d  = ((blockIdx.x & 3) << 8) + threadIdx.x;
    int b  = bc / NCHUNK, c = bc % NCHUNK;

    float pr, pi; load_phazor(phz, d, pr, pi);
    float ir = phz_init[2*d], ii = phz_init[2*d+1];
    float gg = lng[d], bb2 = lnb[d];

    int row0 = b*LL + c*CHUNK;
    const float*  xp  = x + (size_t)row0 * DIMC + d;
    const float2* stp = g_stat + row0;
    float*        yp  = g_y1 + (size_t)row0 * DIMC + d;

    float2 st0 = g_initS[(size_t)bc*DIMC + d];
    float sr = st0.x, si = st0.y;
    #pragma unroll 4
    for (int s = 0; s < CHUNK; s++) {
        float2 st = stp[s];
        float xv = xp[(size_t)s*DIMC];
        float hv = (xv - st.x) * st.y * gg + bb2;
        float nr = pr*sr - pi*si + ir*hv;
        float ni = pr*si + pi*sr + ii*hv;
        sr = nr; si = ni;
        yp[(size_t)s*DIMC] = sr + xv;
    }
}

// ---------------------------------------------------------------------------
// Transpose + convert: in f32 [R][C] -> out fp16 [C][R]
// ---------------------------------------------------------------------------
__global__ __launch_bounds__(256) void convT_kernel(
    const float* __restrict__ in, __half* __restrict__ out, int R, int C)
{
    __shared__ float t[32][33];
    int bx = blockIdx.x * 32, by = blockIdx.y * 32;
    int x = threadIdx.x, y = threadIdx.y;
    #pragma unroll
    for (int i = 0; i < 32; i += 8)
        t[y + i][x] = in[(size_t)(by + y + i) * C + bx + x];
    __syncthreads();
    #pragma unroll
    for (int i = 0; i < 32; i += 8)
        out[(size_t)(bx + y + i) * R + by + x] = __float2half(t[x][y + i]);
}

// ---------------------------------------------------------------------------
// FP16 mma.sync GEMM: C[M,N] = A[M,K] @ Bt[N,K]^T, both fp16 K-major.
// CTA 128x128, BK=32, 8 warps (2x4) of 64x32, 3-stage cp.async, 2 CTA/SM.
// Fragments via ldmatrix.m8n8.x4 (non-trans for both A and B, K-major).
// MODE 0: C = fp16( silu(AB + bias) );  MODE 1: C = f32( AB + bias + resid )
// ---------------------------------------------------------------------------
template<int MODE>
__global__ __launch_bounds__(256, 2) void mma_gemm(
    const __half* __restrict__ A, const __half* __restrict__ Bt,
    const float* __restrict__ bias, const float* __restrict__ resid,
    void* __restrict__ Cv, int M, int N, int K)
{
    constexpr int NT = 4;                             // n-subtiles per warp

    extern __shared__ char dsm[];
    uint32_t sbase = (uint32_t)__cvta_generic_to_shared(dsm);

    int tid  = threadIdx.x;
    int wid  = tid >> 5, lane = tid & 31;
    int g    = lane >> 2, c = lane & 3;
    int wm   = wid >> 2, wn = wid & 3;                // 2 x 4 warps
    int bm   = blockIdx.y * BM;
    int bn   = blockIdx.x * BNT;

    float acc[4][NT][4];
    #pragma unroll
    for (int mt = 0; mt < 4; mt++)
        #pragma unroll
        for (int nt = 0; nt < NT; nt++)
            #pragma unroll
            for (int i = 0; i < 4; i++) acc[mt][nt][i] = 0.f;

    const __half* Abase = A  + (size_t)bm * K;
    const __half* Bbase = Bt + (size_t)bn * K;

    int arow = tid >> 2, aq = tid & 3;                // 16B chunk coords

    auto load_tile = [&](int k0, int stage) {
        uint32_t sa = sbase + (uint32_t)stage * STAGE_BYTES;
        uint32_t sb = sa + A_SMEM_BYTES;
        #pragma unroll
        for (int i = 0; i < 2; i++) {                 // A: 512 chunks
            int row = arow + i * 64;
            cp16(sa + (uint32_t)row * (ASTRH*2) + aq * 16,
                 Abase + (size_t)row * K + k0 + aq * 8);
        }
        #pragma unroll
        for (int i = 0; i < 2; i++) {                 // B: 512 chunks
            int row = arow + i * 64;
            cp16(sb + (uint32_t)row * (ASTRH*2) + aq * 16,
                 Bbase + (size_t)row * K + k0 + aq * 8);
        }
        cp_commit();
    };

    // ldmatrix per-lane base offset: row (lane&15), k-half (lane>>4)*8
    uint32_t lmo = (uint32_t)(lane & 15) * (ASTRH*2) + (uint32_t)(lane >> 4) * 16;
    uint32_t a_lm = lmo + (uint32_t)(wm * 64) * (ASTRH*2);
    uint32_t b_lm = lmo + (uint32_t)A_SMEM_BYTES + (uint32_t)(wn * 32) * (ASTRH*2);

    int NK = K / BKT;
    #pragma unroll
    for (int p = 0; p < STAGES - 1; p++) load_tile(p * BKT, p);

    for (int k = 0; k < NK; k++) {
        cp_wait<STAGES - 2>();
        __syncthreads();

        int nk = k + STAGES - 1;
        if (nk < NK) load_tile(nk * BKT, nk % STAGES);
        else         cp_commit();                     // keep wait counts exact

        uint32_t stg = sbase + (uint32_t)(k % STAGES) * STAGE_BYTES;

        #pragma unroll
        for (int ks = 0; ks < 2; ks++) {
            uint32_t af[4][4], bf[NT][2];
            #pragma unroll
            for (int mt = 0; mt < 4; mt++)
                ldsm_x4(af[mt][0], af[mt][1], af[mt][2], af[mt][3],
                        stg + a_lm + (uint32_t)mt * (16*ASTRH*2) + (uint32_t)ks * 32);
            #pragma unroll
            for (int ntp = 0; ntp < NT/2; ntp++) {
                uint32_t r0, r1, r2, r3;
                ldsm_x4(r0, r1, r2, r3,
                        stg + b_lm + (uint32_t)ntp * (16*ASTRH*2) + (uint32_t)ks * 32);
                bf[2*ntp][0]   = r0; bf[2*ntp+1][0] = r1;
                bf[2*ntp][1]   = r2; bf[2*ntp+1][1] = r3;
            }
            #pragma unroll
            for (int mt = 0; mt < 4; mt++)
                #pragma unroll
                for (int nt = 0; nt < NT; nt++)
                    mma_f16(acc[mt][nt], af[mt], bf[nt]);
        }
    }
    cp_wait<0>();

    // Epilogue: D fragment rows (r0, r0+8), cols (col, col+1)
    #pragma unroll
    for (int mt = 0; mt < 4; mt++) {
        int r0 = bm + wm*64 + mt*16 + g;
        size_t ro0 = (size_t)r0 * N;
        size_t ro1 = (size_t)(r0 + 8) * N;
        #pragma unroll
        for (int nt = 0; nt < NT; nt++) {
            int col = bn + wn*32 + nt*8 + 2*c;
            float2 bs = *(const float2*)(bias + col);
            float v0 = acc[mt][nt][0] + bs.x, v1 = acc[mt][nt][1] + bs.y;
            float v2 = acc[mt][nt][2] + bs.x, v3 = acc[mt][nt][3] + bs.y;
            if (MODE == 0) {
                v0 = v0 / (1.f + __expf(-v0));
                v1 = v1 / (1.f + __expf(-v1));
                v2 = v2 / (1.f + __expf(-v2));
                v3 = v3 / (1.f + __expf(-v3));
                __half* C16 = (__half*)Cv;
                *(__half2*)(C16 + ro0 + col) = __floats2half2_rn(v0, v1);
                *(__half2*)(C16 + ro1 + col) = __floats2half2_rn(v2, v3);
            } else {
                float* C = (float*)Cv;
                float2 r0v = *(const float2*)(resid + ro0 + col);
                float2 r1v = *(const float2*)(resid + ro1 + col);
                *(float2*)(C + ro0 + col) = make_float2(v0 + r0v.x, v1 + r0v.y);
                *(float2*)(C + ro1 + col) = make_float2(v2 + r1v.x, v3 + r1v.y);
            }
        }
    }
}

// ---------------------------------------------------------------------------
// Launch
// ---------------------------------------------------------------------------
extern "C" void kernel_launch(void* const* d_in, const int* in_sizes, int n_in,
                              void* d_out, int out_size)
{
    (void)in_sizes; (void)n_in; (void)out_size;
    const float* x        = (const float*)d_in[0];
    const float* ln_g     = (const float*)d_in[1];
    const float* ln_b     = (const float*)d_in[2];
    const float* phz      = (const float*)d_in[3];
    const float* phz_init = (const float*)d_in[4];
    const float* w1       = (const float*)d_in[5];
    const float* b1       = (const float*)d_in[6];
    const float* w2       = (const float*)d_in[7];
    const float* b2       = (const float*)d_in[8];
    const float* last_re  = (const float*)d_in[9];
    const float* last_im  = (const float*)d_in[10];
    float* out = (float*)d_out;

    float  *y1_p;
    float2 *stat_p;
    __half *h16_p, *act_p, *w1t_p, *w2t_p;
    cudaGetSymbolAddress((void**)&y1_p,  g_y1);
    cudaGetSymbolAddress((void**)&stat_p, g_stat);
    cudaGetSymbolAddress((void**)&h16_p, g_h16);
    cudaGetSymbolAddress((void**)&act_p, g_act16);
    cudaGetSymbolAddress((void**)&w1t_p, g_w1t);
    cudaGetSymbolAddress((void**)&w2t_p, g_w2t);

    cudaFuncSetAttribute((const void*)mma_gemm<0>,
                         cudaFuncAttributeMaxDynamicSharedMemorySize, GSMEM);
    cudaFuncSetAttribute((const void*)mma_gemm<1>,
                         cudaFuncAttributeMaxDynamicSharedMemorySize, GSMEM);

    // 0) weights -> K-major fp16
    {
        dim3 blk(32, 8);
        convT_kernel<<<dim3(DFFC/32, DIMC/32), blk>>>(w1, w1t_p, DIMC, DFFC);
        convT_kernel<<<dim3(DIMC/32, DFFC/32), blk>>>(w2, w2t_p, DFFC, DIMC);
    }

    // 1) LN1 stats (mu, rs) per row — normalization fused into spiral passes
    rowstats_kernel<<<MROWS, 256>>>(x, stat_p);

    // 2) spiral conv (chunked scan, LN1 applied on the fly) + residual -> y1
    spiral_pass1<<<BB*NCHUNK*(DIMC/256), 256>>>(x, phz, phz_init, ln_g, ln_b);
    spiral_pass2<<<(BB*DIMC + 255)/256, 256>>>(phz, last_re, last_im);
    spiral_pass3<<<BB*NCHUNK*(DIMC/256), 256>>>(x, phz, phz_init, ln_g, ln_b);

    // 3) h2 = LN(y1)  (fp16 for GEMM1)
    ln2_kernel<<<MROWS, 256>>>(y1_p, ln_g, ln_b, h16_p);

    // 4) act16 = fp16(silu(h2 @ w1 + b1))   [fp16 mma.sync + ldmatrix]
    {
        dim3 grid(DFFC / BNT, MROWS / BM);
        mma_gemm<0><<<grid, 256, GSMEM>>>(h16_p, w1t_p, b1, nullptr,
                                          act_p, MROWS, DFFC, DIMC);
    }
    // 5) out = act16 @ w2 + b2 + y1   [fp16 mma.sync + ldmatrix]
    {
        dim3 grid(DIMC / BNT, MROWS / BM);
        mma_gemm<1><<<grid, 256, GSMEM>>>(act_p, w2t_p, b2, y1_p,
                                          out, MROWS, DIMC, DFFC);
    }
}

// round 11
// speedup vs baseline: 5.3038x; 1.0203x over previous
#include <cuda_runtime.h>
#include <cuda_fp16.h>
#include <math.h>
#include <stdint.h>

// ---------------------------------------------------------------------------
// Problem constants
// ---------------------------------------------------------------------------
#define BB   4
#define LL   2048
#define DIMC 1024
#define DFFC 4096
#define MROWS (BB*LL)        // 8192
#define NCHUNK 64
#define CHUNK  (LL/NCHUNK)   // 32
#define EPSLN 1e-5f

// GEMM tiling (fp16 mma.sync m16n8k16, fp32 accumulate)
#define BM 128
#define BNT 128
#define BKT 32               // halves of K per stage
#define ASTRH 40             // smem row stride in halves (80B) -> conflict-free
#define STAGES 3
#define STAGE_BYTES ((BM + BNT) * ASTRH * 2)     // 20480
#define GSMEM (STAGES * STAGE_BYTES)             // 61440 (x2 CTA/SM = 122880)
#define A_SMEM_BYTES (BM * ASTRH * 2)

#define G1_MT (MROWS/BM)     // 64 m-tiles
#define G1_NT (DFFC/BNT)     // 32 n-tiles
#define G1_TILES (G1_MT*G1_NT)   // 2048
#define G2_NT (DIMC/BNT)     // 8 n-tiles
#define G2_TILES (G1_MT*G2_NT)   // 512

// prep kernel block ranges
#define CV1_BLKS ((DFFC/32)*(DIMC/32))   // 4096
#define CV2_BLKS ((DIMC/32)*(DFFC/32))   // 4096

// ---------------------------------------------------------------------------
// Scratch (device globals: allocation-free rule)
// ---------------------------------------------------------------------------
__device__ float  g_y1[(size_t)MROWS*DIMC];      // conv + x residual (f32)
__device__ __half g_h16[(size_t)MROWS*DIMC];     // LN2 out (fp16, GEMM1 A)
__device__ __half g_act16[(size_t)MROWS*DFFC];   // silu FFN mid (fp16, GEMM2 A)
__device__ __half g_w1t[(size_t)DFFC*DIMC];      // w1^T fp16 [DFF][DIM]
__device__ __half g_w2t[(size_t)DIMC*DFFC];      // w2^T fp16 [DIM][DFF]
__device__ float2 g_stat[MROWS];                 // LN1 (mu, rsqrt) per row
__device__ float2 g_chunkS[BB*NCHUNK*DIMC];
__device__ float2 g_initS[BB*NCHUNK*DIMC];
__device__ int    g_cnt[G1_MT];                  // per-m-tile arrive counters

// ---------------------------------------------------------------------------
// PTX helpers (base ISA: cp.async + ldmatrix + mma.sync fp16)
// ---------------------------------------------------------------------------
__device__ __forceinline__ void cp16(uint32_t s, const void* gp) {
    asm volatile("cp.async.cg.shared.global [%0], [%1], 16;"
                 :: "r"(s), "l"(gp) : "memory");
}
__device__ __forceinline__ void cp_commit() {
    asm volatile("cp.async.commit_group;" ::: "memory");
}
template<int N> __device__ __forceinline__ void cp_wait() {
    asm volatile("cp.async.wait_group %0;" :: "n"(N) : "memory");
}
__device__ __forceinline__ void ldsm_x4(uint32_t& r0, uint32_t& r1,
                                        uint32_t& r2, uint32_t& r3, uint32_t a) {
    asm volatile("ldmatrix.sync.aligned.m8n8.x4.shared.b16 {%0,%1,%2,%3}, [%4];"
                 : "=r"(r0), "=r"(r1), "=r"(r2), "=r"(r3) : "r"(a));
}
__device__ __forceinline__ void mma_f16(float* d, const uint32_t* a, const uint32_t* b) {
    asm volatile("mma.sync.aligned.m16n8k16.row.col.f32.f16.f16.f32 "
                 "{%0,%1,%2,%3}, {%4,%5,%6,%7}, {%8,%9}, {%0,%1,%2,%3};"
                 : "+f"(d[0]), "+f"(d[1]), "+f"(d[2]), "+f"(d[3])
                 : "r"(a[0]), "r"(a[1]), "r"(a[2]), "r"(a[3]),
                   "r"(b[0]), "r"(b[1]));
}
__device__ __forceinline__ int ld_acquire(const int* p) {
    int v;
    asm volatile("ld.global.acquire.gpu.b32 %0, [%1];" : "=r"(v) : "l"(p) : "memory");
    return v;
}

// ---------------------------------------------------------------------------
// Row reduction helper (256 threads, D=1024 as float4)
// ---------------------------------------------------------------------------
__device__ __forceinline__ void row_stats(float4 v, float& mu, float& rs) {
    float s  = v.x + v.y + v.z + v.w;
    float sq = v.x*v.x + v.y*v.y + v.z*v.z + v.w*v.w;
    #pragma unroll
    for (int o = 16; o > 0; o >>= 1) {
        s  += __shfl_xor_sync(0xffffffffu, s,  o);
        sq += __shfl_xor_sync(0xffffffffu, sq, o);
    }
    __shared__ float ss[8], ssq[8];
    int w = threadIdx.x >> 5, lane = threadIdx.x & 31;
    if (lane == 0) { ss[w] = s; ssq[w] = sq; }
    __syncthreads();
    s = 0.f; sq = 0.f;
    #pragma unroll
    for (int i = 0; i < 8; i++) { s += ss[i]; sq += ssq[i]; }
    mu = s * (1.0f / DIMC);
    float var = sq * (1.0f / DIMC) - mu * mu;
    rs = rsqrtf(var + EPSLN);
}

// ---------------------------------------------------------------------------
// Prep kernel: rowstats(x) | convT(w1) | convT(w2) | zero counters
// Block ranges: [0,MROWS) rowstats, [MROWS,+CV1) w1, [+CV1,+CV2) w2
// ---------------------------------------------------------------------------
__device__ __forceinline__ void convT_body(
    const float* __restrict__ in, __half* __restrict__ out,
    int R, int C, int bx, int by)
{
    __shared__ float t[32][33];
    int x = threadIdx.x & 31, y = threadIdx.x >> 5;   // 32 x 8
    #pragma unroll
    for (int i = 0; i < 32; i += 8)
        t[y + i][x] = in[(size_t)(by*32 + y + i) * C + bx*32 + x];
    __syncthreads();
    #pragma unroll
    for (int i = 0; i < 32; i += 8)
        out[(size_t)(bx*32 + y + i) * R + by*32 + x] = __float2half(t[x][y + i]);
}

__global__ __launch_bounds__(256) void prep_kernel(
    const float* __restrict__ x, float2* __restrict__ stat,
    const float* __restrict__ w1, __half* __restrict__ w1t,
    const float* __restrict__ w2, __half* __restrict__ w2t)
{
    int bid = blockIdx.x;
    if (bid < MROWS) {
        if (bid == 0 && threadIdx.x < G1_MT) g_cnt[threadIdx.x] = 0;
        float4 v = ((const float4*)(x + (size_t)bid * DIMC))[threadIdx.x];
        float mu, rs; row_stats(v, mu, rs);
        if (threadIdx.x == 0) stat[bid] = make_float2(mu, rs);
    } else if (bid < MROWS + CV1_BLKS) {
        int b2 = bid - MROWS;
        convT_body(w1, w1t, DIMC, DFFC, b2 % (DFFC/32), b2 / (DFFC/32));
    } else {
        int b3 = bid - MROWS - CV1_BLKS;
        convT_body(w2, w2t, DFFC, DIMC, b3 % (DIMC/32), b3 / (DIMC/32));
    }
}

// LN2: full layernorm of y1 -> fp16
__global__ __launch_bounds__(256) void ln2_kernel(
    const float* __restrict__ x, const float* __restrict__ g,
    const float* __restrict__ b, __half* __restrict__ out)
{
    int row = blockIdx.x;
    size_t base = (size_t)row * DIMC;
    float4 v = ((const float4*)(x + base))[threadIdx.x];
    float mu, rs; row_stats(v, mu, rs);

    float4 gg = ((const float4*)g)[threadIdx.x];
    float4 bb = ((const float4*)b)[threadIdx.x];
    float ox = (v.x - mu) * rs * gg.x + bb.x;
    float oy = (v.y - mu) * rs * gg.y + bb.y;
    float oz = (v.z - mu) * rs * gg.z + bb.z;
    float ow = (v.w - mu) * rs * gg.w + bb.w;
    __half2* oh = (__half2*)(out + base);
    oh[threadIdx.x * 2 + 0] = __floats2half2_rn(ox, oy);
    oh[threadIdx.x * 2 + 1] = __floats2half2_rn(oz, ow);
}

// ---------------------------------------------------------------------------
// Spiral conv as chunked linear recurrence (LN1 fused via g_stat)
// ---------------------------------------------------------------------------
__device__ __forceinline__ void load_phazor(const float* __restrict__ phz, int d,
                                            float& pr, float& pi)
{
    pr = phz[2*d]; pi = phz[2*d+1];
    float pa = sqrtf(pr*pr + pi*pi);
    float sc = expf(-pa) / pa;
    pr *= sc; pi *= sc;
}

__global__ __launch_bounds__(256) void spiral_pass1(
    const float* __restrict__ x, const float* __restrict__ phz,
    const float* __restrict__ phz_init,
    const float* __restrict__ lng, const float* __restrict__ lnb)
{
    int bc = blockIdx.x >> 2;
    int d  = ((blockIdx.x & 3) << 8) + threadIdx.x;
    int b  = bc / NCHUNK, c = bc % NCHUNK;

    float pr, pi; load_phazor(phz, d, pr, pi);
    float ir = phz_init[2*d], ii = phz_init[2*d+1];
    float gg = lng[d], bb2 = lnb[d];

    int row0 = b*LL + c*CHUNK;
    const float*  xp  = x + (size_t)row0 * DIMC + d;
    const float2* stp = g_stat + row0;

    float sr = 0.f, si = 0.f;
    #pragma unroll 8
    for (int s = 0; s < CHUNK; s++) {
        float2 st = stp[s];
        float hv = (xp[(size_t)s*DIMC] - st.x) * st.y * gg + bb2;
        float nr = pr*sr - pi*si + ir*hv;
        float ni = pr*si + pi*sr + ii*hv;
        sr = nr; si = ni;
    }
    g_chunkS[(size_t)bc*DIMC + d] = make_float2(sr, si);
}

__global__ void spiral_pass2(
    const float* __restrict__ phz,
    const float* __restrict__ last_re, const float* __restrict__ last_im)
{
    int idx = blockIdx.x * blockDim.x + threadIdx.x;
    if (idx >= BB * DIMC) return;
    int b = idx / DIMC, d = idx % DIMC;

    float pr, pi; load_phazor(phz, d, pr, pi);
    float cr = pr, ci = pi;               // p̂^CHUNK via 5 squarings (CHUNK=32)
    #pragma unroll
    for (int i = 0; i < 5; i++) {
        float nr = cr*cr - ci*ci;
        ci = 2.f*cr*ci; cr = nr;
    }
    float sr = last_re[idx], si = last_im[idx];
    #pragma unroll 8
    for (int c = 0; c < NCHUNK; c++) {
        size_t off = ((size_t)b*NCHUNK + c)*DIMC + d;
        g_initS[off] = make_float2(sr, si);
        float2 S = g_chunkS[off];
        float nr = cr*sr - ci*si + S.x;
        float ni = cr*si + ci*sr + S.y;
        sr = nr; si = ni;
    }
}

__global__ __launch_bounds__(256) void spiral_pass3(
    const float* __restrict__ x, const float* __restrict__ phz,
    const float* __restrict__ phz_init,
    const float* __restrict__ lng, const float* __restrict__ lnb)
{
    int bc = blockIdx.x >> 2;
    int d  = ((blockIdx.x & 3) << 8) + threadIdx.x;
    int b  = bc / NCHUNK, c = bc % NCHUNK;

    float pr, pi; load_phazor(phz, d, pr, pi);
    float ir = phz_init[2*d], ii = phz_init[2*d+1];
    float gg = lng[d], bb2 = lnb[d];

    int row0 = b*LL + c*CHUNK;
    const float*  xp  = x + (size_t)row0 * DIMC + d;
    const float2* stp = g_stat + row0;
    float*        yp  = g_y1 + (size_t)row0 * DIMC + d;

    float2 st0 = g_initS[(size_t)bc*DIMC + d];
    float sr = st0.x, si = st0.y;
    #pragma unroll 4
    for (int s = 0; s < CHUNK; s++) {
        float2 st = stp[s];
        float xv = xp[(size_t)s*DIMC];
        float hv = (xv - st.x) * st.y * gg + bb2;
        float nr = pr*sr - pi*si + ir*hv;
        float ni = pr*si + pi*sr + ii*hv;
        sr = nr; si = ni;
        yp[(size_t)s*DIMC] = sr + xv;
    }
}

// ---------------------------------------------------------------------------
// GEMM tile body: C[128,128] tile of A[M,KK] @ Bt[NN,KK]^T (fp16 K-major).
// BK=32, 8 warps (2x4) of 64x32, 3-stage cp.async, ldmatrix fragments.
// MODE 0: C = fp16( silu(AB + bias) );  MODE 1: C = f32( AB + bias + resid )
// ---------------------------------------------------------------------------
template<int MODE, int NN, int KK>
__device__ __forceinline__ void gemm_body(
    const __half* __restrict__ A, const __half* __restrict__ Bt,
    const float* __restrict__ bias, const float* __restrict__ resid,
    void* __restrict__ Cv, int bm, int bn, char* dsm)
{
    constexpr int NT = 4;
    constexpr int NK = KK / BKT;

    uint32_t sbase = (uint32_t)__cvta_generic_to_shared(dsm);

    int tid  = threadIdx.x;
    int wid  = tid >> 5, lane = tid & 31;
    int g    = lane >> 2, c = lane & 3;
    int wm   = wid >> 2, wn = wid & 3;

    float acc[4][NT][4];
    #pragma unroll
    for (int mt = 0; mt < 4; mt++)
        #pragma unroll
        for (int nt = 0; nt < NT; nt++)
            #pragma unroll
            for (int i = 0; i < 4; i++) acc[mt][nt][i] = 0.f;

    const __half* Abase = A  + (size_t)bm * KK;
    const __half* Bbase = Bt + (size_t)bn * KK;

    int arow = tid >> 2, aq = tid & 3;

    auto load_tile = [&](int k0, int stage) {
        uint32_t sa = sbase + (uint32_t)stage * STAGE_BYTES;
        uint32_t sb = sa + A_SMEM_BYTES;
        #pragma unroll
        for (int i = 0; i < 2; i++) {
            int row = arow + i * 64;
            cp16(sa + (uint32_t)row * (ASTRH*2) + aq * 16,
                 Abase + (size_t)row * KK + k0 + aq * 8);
        }
        #pragma unroll
        for (int i = 0; i < 2; i++) {
            int row = arow + i * 64;
            cp16(sb + (uint32_t)row * (ASTRH*2) + aq * 16,
                 Bbase + (size_t)row * KK + k0 + aq * 8);
        }
        cp_commit();
    };

    uint32_t lmo = (uint32_t)(lane & 15) * (ASTRH*2) + (uint32_t)(lane >> 4) * 16;
    uint32_t a_lm = lmo + (uint32_t)(wm * 64) * (ASTRH*2);
    uint32_t b_lm = lmo + (uint32_t)A_SMEM_BYTES + (uint32_t)(wn * 32) * (ASTRH*2);

    #pragma unroll
    for (int p = 0; p < STAGES - 1; p++) load_tile(p * BKT, p);

    for (int k = 0; k < NK; k++) {
        cp_wait<STAGES - 2>();
        __syncthreads();

        int nk = k + STAGES - 1;
        if (nk < NK) load_tile(nk * BKT, nk % STAGES);
        else         cp_commit();

        uint32_t stg = sbase + (uint32_t)(k % STAGES) * STAGE_BYTES;

        #pragma unroll
        for (int ks = 0; ks < 2; ks++) {
            uint32_t af[4][4], bf[NT][2];
            #pragma unroll
            for (int mt = 0; mt < 4; mt++)
                ldsm_x4(af[mt][0], af[mt][1], af[mt][2], af[mt][3],
                        stg + a_lm + (uint32_t)mt * (16*ASTRH*2) + (uint32_t)ks * 32);
            #pragma unroll
            for (int ntp = 0; ntp < NT/2; ntp++) {
                uint32_t r0, r1, r2, r3;
                ldsm_x4(r0, r1, r2, r3,
                        stg + b_lm + (uint32_t)ntp * (16*ASTRH*2) + (uint32_t)ks * 32);
                bf[2*ntp][0]   = r0; bf[2*ntp+1][0] = r1;
                bf[2*ntp][1]   = r2; bf[2*ntp+1][1] = r3;
            }
            #pragma unroll
            for (int mt = 0; mt < 4; mt++)
                #pragma unroll
                for (int nt = 0; nt < NT; nt++)
                    mma_f16(acc[mt][nt], af[mt], bf[nt]);
        }
    }
    cp_wait<0>();

    #pragma unroll
    for (int mt = 0; mt < 4; mt++) {
        int r0 = bm + wm*64 + mt*16 + g;
        size_t ro0 = (size_t)r0 * NN;
        size_t ro1 = (size_t)(r0 + 8) * NN;
        #pragma unroll
        for (int nt = 0; nt < NT; nt++) {
            int col = bn + wn*32 + nt*8 + 2*c;
            float2 bs = *(const float2*)(bias + col);
            float v0 = acc[mt][nt][0] + bs.x, v1 = acc[mt][nt][1] + bs.y;
            float v2 = acc[mt][nt][2] + bs.x, v3 = acc[mt][nt][3] + bs.y;
            if (MODE == 0) {
                v0 = v0 / (1.f + __expf(-v0));
                v1 = v1 / (1.f + __expf(-v1));
                v2 = v2 / (1.f + __expf(-v2));
                v3 = v3 / (1.f + __expf(-v3));
                __half* C16 = (__half*)Cv;
                *(__half2*)(C16 + ro0 + col) = __floats2half2_rn(v0, v1);
                *(__half2*)(C16 + ro1 + col) = __floats2half2_rn(v2, v3);
            } else {
                float* C = (float*)Cv;
                float2 r0v = *(const float2*)(resid + ro0 + col);
                float2 r1v = *(const float2*)(resid + ro1 + col);
                *(float2*)(C + ro0 + col) = make_float2(v0 + r0v.x, v1 + r0v.y);
                *(float2*)(C + ro1 + col) = make_float2(v2 + r1v.x, v3 + r1v.y);
            }
        }
    }
}

// ---------------------------------------------------------------------------
// Fused FFN: GEMM1 tiles (0..2047) produce act16 and signal cnt[m];
// GEMM2 tiles (2048..2559) spin-wait cnt[m]==32 then consume.
// ---------------------------------------------------------------------------
__global__ __launch_bounds__(256, 2) void fused_ffn(
    const __half* __restrict__ h16, const __half* __restrict__ w1t,
    const float* __restrict__ b1,
    __half* __restrict__ act16, const __half* __restrict__ w2t,
    const float* __restrict__ b2, const float* __restrict__ y1,
    float* __restrict__ out)
{
    extern __shared__ char dsm[];
    int bid = blockIdx.x;

    if (bid < G1_TILES) {
        int m = bid >> 5, n = bid & 31;              // n fastest within m
        gemm_body<0, DFFC, DIMC>(h16, w1t, b1, nullptr, act16,
                                 m * BM, n * BNT, dsm);
        __threadfence();                             // each thread's stores -> gpu
        __syncthreads();                             // all threads fenced
        if (threadIdx.x == 0) atomicAdd(&g_cnt[m], 1);
    } else {
        int b2i = bid - G1_TILES;
        int m = b2i >> 3, n = b2i & 7;
        if (threadIdx.x == 0) {
            while (ld_acquire(&g_cnt[m]) < G1_NT) __nanosleep(128);
        }
        __syncthreads();
        __threadfence();                             // acquire ordering for loads
        gemm_body<1, DIMC, DFFC>(act16, w2t, b2, y1, out,
                                 m * BM, n * BNT, dsm);
    }
}

// ---------------------------------------------------------------------------
// Launch
// ---------------------------------------------------------------------------
extern "C" void kernel_launch(void* const* d_in, const int* in_sizes, int n_in,
                              void* d_out, int out_size)
{
    (void)in_sizes; (void)n_in; (void)out_size;
    const float* x        = (const float*)d_in[0];
    const float* ln_g     = (const float*)d_in[1];
    const float* ln_b     = (const float*)d_in[2];
    const float* phz      = (const float*)d_in[3];
    const float* phz_init = (const float*)d_in[4];
    const float* w1       = (const float*)d_in[5];
    const float* b1       = (const float*)d_in[6];
    const float* w2       = (const float*)d_in[7];
    const float* b2       = (const float*)d_in[8];
    const float* last_re  = (const float*)d_in[9];
    const float* last_im  = (const float*)d_in[10];
    float* out = (float*)d_out;

    float  *y1_p;
    float2 *stat_p;
    __half *h16_p, *act_p, *w1t_p, *w2t_p;
    cudaGetSymbolAddress((void**)&y1_p,   g_y1);
    cudaGetSymbolAddress((void**)&stat_p, g_stat);
    cudaGetSymbolAddress((void**)&h16_p,  g_h16);
    cudaGetSymbolAddress((void**)&act_p,  g_act16);
    cudaGetSymbolAddress((void**)&w1t_p,  g_w1t);
    cudaGetSymbolAddress((void**)&w2t_p,  g_w2t);

    cudaFuncSetAttribute((const void*)fused_ffn,
                         cudaFuncAttributeMaxDynamicSharedMemorySize, GSMEM);

    // 1) prep: LN1 rowstats + weight converts + zero arrive counters
    prep_kernel<<<MROWS + CV1_BLKS + CV2_BLKS, 256>>>(x, stat_p, w1, w1t_p, w2, w2t_p);

    // 2) spiral conv (chunked scan, LN1 applied on the fly) + residual -> y1
    spiral_pass1<<<BB*NCHUNK*(DIMC/256), 256>>>(x, phz, phz_init, ln_g, ln_b);
    spiral_pass2<<<(BB*DIMC + 255)/256, 256>>>(phz, last_re, last_im);
    spiral_pass3<<<BB*NCHUNK*(DIMC/256), 256>>>(x, phz, phz_init, ln_g, ln_b);

    // 3) h2 = LN(y1)  (fp16 for GEMM1)
    ln2_kernel<<<MROWS, 256>>>(y1_p, ln_g, ln_b, h16_p);

    // 4+5) fused FFN: GEMM1 -> (flags) -> GEMM2, one launch
    fused_ffn<<<G1_TILES + G2_TILES, 256, GSMEM>>>(
        h16_p, w1t_p, b1, act_p, w2t_p, b2, y1_p, out);
}